// round 3
// baseline (speedup 1.0000x reference)
#include <cuda_runtime.h>
#include <math.h>

#define B_   8
#define SP_  800
#define SS_  48
#define NT_  848
#define DP_  2048
#define DS_  1024
#define DC_  1024
#define H_   8
#define HD_  256
#define FP_  16384
#define FS_  4096
#define EPS_ 1e-6f
#define MASKV_ (-2.3819763e+38f)

// ---------------- scratch (static device allocations) ----------------
__device__ float g_hp  [(size_t)B_*SP_*DP_];        // prefix norm out / post-norm reuse
__device__ float g_mod1[B_*3*DS_];
__device__ float g_mod2[B_*3*DS_];
__device__ float g_hs  [B_*SS_*DS_];                // suffix norm out / reuse
__device__ float g_q   [(size_t)B_*NT_*H_*HD_];
__device__ float g_k   [(size_t)B_*NT_*HD_];
__device__ float g_v   [(size_t)B_*NT_*HD_];
__device__ float g_sc  [(size_t)B_*H_*NT_*NT_];     // scores / attn probs
__device__ float g_ao  [(size_t)B_*NT_*H_*HD_];     // attention output
__device__ float g_resp[(size_t)B_*SP_*DP_];
__device__ float g_act [(size_t)B_*SP_*FP_];        // prefix mlp activation
__device__ float g_ress[B_*SS_*DS_];
__device__ float g_sact[B_*SS_*FS_];                // suffix mlp activation

// ---------------- generic batched GEMM with fused epilogues ----------------
// C[m,n] = alpha * sum_k A[m,k] * B(n,k)   (transB=0: B is [N,K]; transB=1: B is [K,N])
struct GemmP {
    const float* A; const float* Bm; float* C;
    int M, N, K, lda, ldb, ldc;
    long long sA, sB, sC, sA2, sB2, sC2;   // batch strides: z -> (z/zdiv)*s + (z%zdiv)*s2
    int zdiv;
    int transB;
    int epi;        // 0 plain, 1 +bias[n], 2 gelu, 3 C[m,n]*acc (in-place aux), 4 +res, 5 res + acc*gate, 6 mask+scale
    float alpha;
    const float* bias;
    const float* res;  long long sRes;
    const float* gate; long long sGate; int rowsPerB; int ldGate;
};

__device__ __forceinline__ float gelu_tanh(float x) {
    float x3 = x * x * x;
    return 0.5f * x * (1.0f + tanhf(0.7978845608028654f * (x + 0.044715f * x3)));
}

__global__ __launch_bounds__(256) void gemm_kernel(GemmP p) {
    const int z  = blockIdx.z;
    const int zb = z / p.zdiv, zr = z % p.zdiv;
    const float* A  = p.A  + (long long)zb * p.sA + (long long)zr * p.sA2;
    const float* Bm = p.Bm + (long long)zb * p.sB + (long long)zr * p.sB2;
    float*       C  = p.C  + (long long)zb * p.sC + (long long)zr * p.sC2;

    __shared__ float As[8][128];
    __shared__ float Bs[8][128];

    const int tid = threadIdx.x;
    const int bm = blockIdx.y * 128;
    const int bn = blockIdx.x * 128;
    const int tx = tid & 15;
    const int ty = tid >> 4;

    float acc[8][8];
#pragma unroll
    for (int i = 0; i < 8; i++)
#pragma unroll
        for (int j = 0; j < 8; j++) acc[i][j] = 0.f;

    const int lrow = tid >> 1;          // 0..127
    const int lcol = (tid & 1) * 4;     // 0 or 4
    const int tbr  = tid >> 5;          // 0..7
    const int tbc  = (tid & 31) * 4;    // 0..124

    for (int k0 = 0; k0 < p.K; k0 += 8) {
        {   // A tile (M,K) row-major -> As[k][m]
            int gm = bm + lrow;
            float4 v = make_float4(0.f, 0.f, 0.f, 0.f);
            if (gm < p.M) v = *(const float4*)(A + (long long)gm * p.lda + (k0 + lcol));
            As[lcol + 0][lrow] = v.x; As[lcol + 1][lrow] = v.y;
            As[lcol + 2][lrow] = v.z; As[lcol + 3][lrow] = v.w;
        }
        if (!p.transB) {   // B tile [N,K] row-major -> Bs[k][n]
            int gn = bn + lrow;
            float4 v = make_float4(0.f, 0.f, 0.f, 0.f);
            if (gn < p.N) v = *(const float4*)(Bm + (long long)gn * p.ldb + (k0 + lcol));
            Bs[lcol + 0][lrow] = v.x; Bs[lcol + 1][lrow] = v.y;
            Bs[lcol + 2][lrow] = v.z; Bs[lcol + 3][lrow] = v.w;
        } else {           // B tile [K,N] row-major -> Bs[k][n]
            int gn = bn + tbc;
            float4 v = make_float4(0.f, 0.f, 0.f, 0.f);
            if (gn < p.N) v = *(const float4*)(Bm + (long long)(k0 + tbr) * p.ldb + gn);
            Bs[tbr][tbc + 0] = v.x; Bs[tbr][tbc + 1] = v.y;
            Bs[tbr][tbc + 2] = v.z; Bs[tbr][tbc + 3] = v.w;
        }
        __syncthreads();
#pragma unroll
        for (int kk = 0; kk < 8; kk++) {
            float ar[8], br[8];
            *(float4*)&ar[0] = *(const float4*)&As[kk][ty * 8];
            *(float4*)&ar[4] = *(const float4*)&As[kk][ty * 8 + 4];
            *(float4*)&br[0] = *(const float4*)&Bs[kk][tx * 8];
            *(float4*)&br[4] = *(const float4*)&Bs[kk][tx * 8 + 4];
#pragma unroll
            for (int i = 0; i < 8; i++)
#pragma unroll
                for (int j = 0; j < 8; j++)
                    acc[i][j] = fmaf(ar[i], br[j], acc[i][j]);
        }
        __syncthreads();
    }

#pragma unroll
    for (int i = 0; i < 8; i++) {
        int m = bm + ty * 8 + i;
        if (m >= p.M) continue;
#pragma unroll
        for (int j = 0; j < 8; j++) {
            int n = bn + tx * 8 + j;
            if (n >= p.N) continue;
            float v = acc[i][j] * p.alpha;
            long long cidx = (long long)m * p.ldc + n;
            switch (p.epi) {
                case 1: v += p.bias[n]; break;
                case 2: v = gelu_tanh(v); break;
                case 3: v = C[cidx] * v; break;
                case 4: v += p.res[(long long)zb * p.sRes + cidx]; break;
                case 5: v = p.res[(long long)zb * p.sRes + cidx]
                            + v * p.gate[(long long)zb * p.sGate
                                         + (long long)(m / p.rowsPerB) * p.ldGate + n];
                        break;
                case 6: if (m < SP_ && n >= SP_) v += MASKV_; break;
                default: break;
            }
            C[cidx] = v;
        }
    }
}

// ---------------- RMS norms ----------------
__global__ __launch_bounds__(256) void rmsnorm_gemma_kernel(
    const float* __restrict__ x, const float* __restrict__ w,
    float* __restrict__ out, int D)
{
    long long row = blockIdx.x;
    const float* xr = x + row * D;
    float* orow = out + row * D;
    float ss = 0.f;
    for (int i = threadIdx.x; i < D; i += 256) { float v = xr[i]; ss = fmaf(v, v, ss); }
    __shared__ float sh[32];
    int lane = threadIdx.x & 31, wid = threadIdx.x >> 5;
#pragma unroll
    for (int o = 16; o > 0; o >>= 1) ss += __shfl_down_sync(0xffffffffu, ss, o);
    if (lane == 0) sh[wid] = ss;
    __syncthreads();
    if (threadIdx.x == 0) {
        float t = 0.f;
        for (int i = 0; i < 8; i++) t += sh[i];
        sh[0] = rsqrtf(t / (float)D + EPS_);
    }
    __syncthreads();
    float r = sh[0];
    for (int i = threadIdx.x; i < D; i += 256) orow[i] = xr[i] * r * (1.0f + w[i]);
}

__global__ __launch_bounds__(256) void ada_norm_kernel(
    const float* __restrict__ x, const float* __restrict__ mod, float* __restrict__ out)
{
    int row = blockIdx.x;                 // b*SS_ + s
    int b = row / SS_;
    const float* xr = x + (long long)row * DS_;
    const float* mrow = mod + (long long)b * 3 * DS_;
    float* orow = out + (long long)row * DS_;
    float ss = 0.f;
    for (int i = threadIdx.x; i < DS_; i += 256) { float v = xr[i]; ss = fmaf(v, v, ss); }
    __shared__ float sh[32];
    int lane = threadIdx.x & 31, wid = threadIdx.x >> 5;
#pragma unroll
    for (int o = 16; o > 0; o >>= 1) ss += __shfl_down_sync(0xffffffffu, ss, o);
    if (lane == 0) sh[wid] = ss;
    __syncthreads();
    if (threadIdx.x == 0) {
        float t = 0.f;
        for (int i = 0; i < 8; i++) t += sh[i];
        sh[0] = rsqrtf(t / (float)DS_ + EPS_);
    }
    __syncthreads();
    float r = sh[0];
    for (int i = threadIdx.x; i < DS_; i += 256)
        orow[i] = xr[i] * r * (1.0f + mrow[i]) + mrow[DS_ + i];
}

// ---------------- RoPE (in place on q and k) ----------------
__global__ void rope_kernel(float* __restrict__ q, float* __restrict__ k) {
    long long idx = (long long)blockIdx.x * blockDim.x + threadIdx.x;
    const long long NQ = (long long)B_ * NT_ * H_ * (HD_ / 2);
    const long long NK = (long long)B_ * NT_ * (HD_ / 2);
    const float LN_TH_OVER = 9.210340371976184f / 128.0f;  // ln(10000)/128
    if (idx < NQ) {
        int d = (int)(idx & 127); long long t = idx >> 7;
        int h = (int)(t % H_); t /= H_;
        int s = (int)(t % NT_); int b = (int)(t / NT_);
        float inv = expf(-(float)d * LN_TH_OVER);
        float ang = (float)s * inv;
        float c, sn; sincosf(ang, &sn, &c);
        float* pq = q + ((long long)(b * NT_ + s)) * (H_ * HD_) + h * HD_;
        float x1 = pq[d], x2 = pq[d + 128];
        pq[d]       = x1 * c - x2 * sn;
        pq[d + 128] = x2 * c + x1 * sn;
    } else if (idx < NQ + NK) {
        long long r = idx - NQ;
        int d = (int)(r & 127); long long t = r >> 7;
        int s = (int)(t % NT_); int b = (int)(t / NT_);
        float inv = expf(-(float)d * LN_TH_OVER);
        float ang = (float)s * inv;
        float c, sn; sincosf(ang, &sn, &c);
        float* pk = k + ((long long)(b * NT_ + s)) * HD_;
        float x1 = pk[d], x2 = pk[d + 128];
        pk[d]       = x1 * c - x2 * sn;
        pk[d + 128] = x2 * c + x1 * sn;
    }
}

// ---------------- softmax over rows of length NT_ ----------------
__global__ __launch_bounds__(256) void softmax_kernel(float* __restrict__ sc) {
    long long row = blockIdx.x;
    float* p = sc + row * NT_;
    __shared__ float sh[32];
    int lane = threadIdx.x & 31, wid = threadIdx.x >> 5;

    float mx = -3.4e38f;
    for (int i = threadIdx.x; i < NT_; i += 256) mx = fmaxf(mx, p[i]);
#pragma unroll
    for (int o = 16; o > 0; o >>= 1) mx = fmaxf(mx, __shfl_down_sync(0xffffffffu, mx, o));
    if (lane == 0) sh[wid] = mx;
    __syncthreads();
    if (threadIdx.x == 0) {
        float t = -3.4e38f;
        for (int i = 0; i < 8; i++) t = fmaxf(t, sh[i]);
        sh[0] = t;
    }
    __syncthreads();
    mx = sh[0];
    __syncthreads();

    float sm = 0.f;
    for (int i = threadIdx.x; i < NT_; i += 256) {
        float e = expf(p[i] - mx);
        p[i] = e;
        sm += e;
    }
#pragma unroll
    for (int o = 16; o > 0; o >>= 1) sm += __shfl_down_sync(0xffffffffu, sm, o);
    if (lane == 0) sh[wid] = sm;
    __syncthreads();
    if (threadIdx.x == 0) {
        float t = 0.f;
        for (int i = 0; i < 8; i++) t += sh[i];
        sh[0] = 1.0f / t;
    }
    __syncthreads();
    float inv = sh[0];
    for (int i = threadIdx.x; i < NT_; i += 256) p[i] *= inv;
}

// ---------------- host side ----------------
static GemmP gp(const float* A, const float* Bm, float* C,
                int M, int N, int K, int lda, int ldb, int ldc) {
    GemmP p = {};
    p.A = A; p.Bm = Bm; p.C = C;
    p.M = M; p.N = N; p.K = K; p.lda = lda; p.ldb = ldb; p.ldc = ldc;
    p.zdiv = 1; p.alpha = 1.0f; p.rowsPerB = 1 << 30;
    return p;
}

static void launch_gemm(const GemmP& p, int batch) {
    dim3 grid((p.N + 127) / 128, (p.M + 127) / 128, batch);
    gemm_kernel<<<grid, 256>>>(p);
}

extern "C" void kernel_launch(void* const* d_in, const int* in_sizes, int n_in,
                              void* d_out, int out_size) {
    const float* prefix_x    = (const float*)d_in[0];
    const float* suffix_x    = (const float*)d_in[1];
    const float* cond        = (const float*)d_in[2];
    const float* p_ln_w      = (const float*)d_in[3];
    const float* p_q_w       = (const float*)d_in[4];
    const float* p_k_w       = (const float*)d_in[5];
    const float* p_v_w       = (const float*)d_in[6];
    const float* p_o_w       = (const float*)d_in[7];
    const float* p_post_ln_w = (const float*)d_in[8];
    const float* p_gate_w    = (const float*)d_in[9];
    const float* p_up_w      = (const float*)d_in[10];
    const float* p_down_w    = (const float*)d_in[11];
    const float* s_ada1_w    = (const float*)d_in[12];
    const float* s_ada1_b    = (const float*)d_in[13];
    const float* s_q_w       = (const float*)d_in[14];
    const float* s_k_w       = (const float*)d_in[15];
    const float* s_v_w       = (const float*)d_in[16];
    const float* s_o_w       = (const float*)d_in[17];
    const float* s_ada2_w    = (const float*)d_in[18];
    const float* s_ada2_b    = (const float*)d_in[19];
    const float* s_gate_w    = (const float*)d_in[20];
    const float* s_up_w      = (const float*)d_in[21];
    const float* s_down_w    = (const float*)d_in[22];
    float* out = (float*)d_out;

    float *hp, *mod1, *mod2, *hs, *q, *k, *v, *sc, *ao, *resp, *act, *ress, *sact;
    cudaGetSymbolAddress((void**)&hp,   g_hp);
    cudaGetSymbolAddress((void**)&mod1, g_mod1);
    cudaGetSymbolAddress((void**)&mod2, g_mod2);
    cudaGetSymbolAddress((void**)&hs,   g_hs);
    cudaGetSymbolAddress((void**)&q,    g_q);
    cudaGetSymbolAddress((void**)&k,    g_k);
    cudaGetSymbolAddress((void**)&v,    g_v);
    cudaGetSymbolAddress((void**)&sc,   g_sc);
    cudaGetSymbolAddress((void**)&ao,   g_ao);
    cudaGetSymbolAddress((void**)&resp, g_resp);
    cudaGetSymbolAddress((void**)&act,  g_act);
    cudaGetSymbolAddress((void**)&ress, g_ress);
    cudaGetSymbolAddress((void**)&sact, g_sact);

    // 1. prefix gemma norm
    rmsnorm_gemma_kernel<<<B_ * SP_, 256>>>(prefix_x, p_ln_w, hp, DP_);

    // 2. adaLN modulation vectors (cond @ W^T + b), both layers
    {
        GemmP p = gp(cond, s_ada1_w, mod1, B_, 3 * DS_, DC_, DC_, DC_, 3 * DS_);
        p.epi = 1; p.bias = s_ada1_b;
        launch_gemm(p, 1);
        GemmP p2 = gp(cond, s_ada2_w, mod2, B_, 3 * DS_, DC_, DC_, DC_, 3 * DS_);
        p2.epi = 1; p2.bias = s_ada2_b;
        launch_gemm(p2, 1);
    }

    // 3. suffix adaLN #1
    ada_norm_kernel<<<B_ * SS_, 256>>>(suffix_x, mod1, hs);

    // 4. QKV projections (batched over B, outputs interleaved prefix|suffix rows)
    {
        GemmP p = gp(hp, p_q_w, q, SP_, H_ * HD_, DP_, DP_, DP_, H_ * HD_);
        p.sA = (long long)SP_ * DP_; p.sC = (long long)NT_ * H_ * HD_;
        launch_gemm(p, B_);
    }
    {
        GemmP p = gp(hs, s_q_w, q + (long long)SP_ * H_ * HD_, SS_, H_ * HD_, DS_, DS_, DS_, H_ * HD_);
        p.sA = (long long)SS_ * DS_; p.sC = (long long)NT_ * H_ * HD_;
        launch_gemm(p, B_);
    }
    {
        GemmP p = gp(hp, p_k_w, k, SP_, HD_, DP_, DP_, DP_, HD_);
        p.sA = (long long)SP_ * DP_; p.sC = (long long)NT_ * HD_;
        launch_gemm(p, B_);
    }
    {
        GemmP p = gp(hs, s_k_w, k + (long long)SP_ * HD_, SS_, HD_, DS_, DS_, DS_, HD_);
        p.sA = (long long)SS_ * DS_; p.sC = (long long)NT_ * HD_;
        launch_gemm(p, B_);
    }
    {
        GemmP p = gp(hp, p_v_w, v, SP_, HD_, DP_, DP_, DP_, HD_);
        p.sA = (long long)SP_ * DP_; p.sC = (long long)NT_ * HD_;
        launch_gemm(p, B_);
    }
    {
        GemmP p = gp(hs, s_v_w, v + (long long)SP_ * HD_, SS_, HD_, DS_, DS_, DS_, HD_);
        p.sA = (long long)SS_ * DS_; p.sC = (long long)NT_ * HD_;
        launch_gemm(p, B_);
    }

    // 5. RoPE on q, k
    {
        long long total = (long long)B_ * NT_ * H_ * (HD_ / 2) + (long long)B_ * NT_ * (HD_ / 2);
        int blocks = (int)((total + 255) / 256);
        rope_kernel<<<blocks, 256>>>(q, k);
    }

    // 6. scores = QK^T/16 + mask   (batched over z = b*H + h)
    {
        GemmP p = gp(q, k, sc, NT_, NT_, HD_, H_ * HD_, HD_, NT_);
        p.zdiv = H_;
        p.sA = (long long)NT_ * H_ * HD_; p.sA2 = HD_;
        p.sB = (long long)NT_ * HD_;      p.sB2 = 0;
        p.sC = (long long)H_ * NT_ * NT_; p.sC2 = (long long)NT_ * NT_;
        p.epi = 6; p.alpha = 0.0625f;
        launch_gemm(p, B_ * H_);
    }

    // 7. softmax
    softmax_kernel<<<B_ * H_ * NT_, 256>>>(sc);

    // 8. attn @ V   (transB: V is [k=seq, n=hd])
    {
        GemmP p = gp(sc, v, ao, NT_, HD_, NT_, NT_, HD_, H_ * HD_);
        p.zdiv = H_; p.transB = 1;
        p.sA = (long long)H_ * NT_ * NT_; p.sA2 = (long long)NT_ * NT_;
        p.sB = (long long)NT_ * HD_;      p.sB2 = 0;
        p.sC = (long long)NT_ * H_ * HD_; p.sC2 = HD_;
        launch_gemm(p, B_ * H_);
    }

    // 9. prefix O-proj + residual -> res_p
    {
        GemmP p = gp(ao, p_o_w, resp, SP_, DP_, H_ * HD_, H_ * HD_, H_ * HD_, DP_);
        p.sA = (long long)NT_ * H_ * HD_; p.sC = (long long)SP_ * DP_;
        p.epi = 4; p.res = prefix_x; p.sRes = (long long)SP_ * DP_;
        launch_gemm(p, B_);
    }

    // 10. post-norm of res_p (reuse hp)
    rmsnorm_gemma_kernel<<<B_ * SP_, 256>>>(resp, p_post_ln_w, hp, DP_);

    // 11-13. prefix MLP: gelu(x@gate^T) * (x@up^T) @ down^T + res_p  -> out_p
    {
        GemmP p = gp(hp, p_gate_w, act, B_ * SP_, FP_, DP_, DP_, DP_, FP_);
        p.epi = 2;
        launch_gemm(p, 1);
    }
    {
        GemmP p = gp(hp, p_up_w, act, B_ * SP_, FP_, DP_, DP_, DP_, FP_);
        p.epi = 3;   // act = gelu_buf * up
        launch_gemm(p, 1);
    }
    {
        GemmP p = gp(act, p_down_w, out, B_ * SP_, DP_, FP_, FP_, FP_, DP_);
        p.epi = 4; p.res = resp; p.sRes = 0;
        launch_gemm(p, 1);
    }

    // 14. suffix O-proj with gate -> res_s
    {
        GemmP p = gp(ao + (long long)SP_ * H_ * HD_, s_o_w, ress, SS_, DS_, H_ * HD_, H_ * HD_, H_ * HD_, DS_);
        p.sA = (long long)NT_ * H_ * HD_; p.sC = (long long)SS_ * DS_;
        p.epi = 5; p.res = suffix_x; p.sRes = (long long)SS_ * DS_;
        p.gate = mod1 + 2 * DS_; p.sGate = 3 * DS_; p.rowsPerB = 1 << 30; p.ldGate = 0;
        launch_gemm(p, B_);
    }

    // 15. suffix adaLN #2 (reuse hs)
    ada_norm_kernel<<<B_ * SS_, 256>>>(ress, mod2, hs);

    // 16-18. suffix MLP with gate2 -> out_s
    {
        GemmP p = gp(hs, s_gate_w, sact, B_ * SS_, FS_, DS_, DS_, DS_, FS_);
        p.epi = 2;
        launch_gemm(p, 1);
    }
    {
        GemmP p = gp(hs, s_up_w, sact, B_ * SS_, FS_, DS_, DS_, DS_, FS_);
        p.epi = 3;
        launch_gemm(p, 1);
    }
    {
        GemmP p = gp(sact, s_down_w, out + (long long)B_ * SP_ * DP_, B_ * SS_, DS_, FS_, FS_, FS_, DS_);
        p.epi = 5; p.res = ress; p.sRes = 0;
        p.gate = mod2 + 2 * DS_; p.sGate = 0; p.rowsPerB = SS_; p.ldGate = 3 * DS_;
        launch_gemm(p, 1);
    }
}

// round 11
// speedup vs baseline: 1.9920x; 1.9920x over previous
#include <cuda_runtime.h>
#include <cuda_bf16.h>
#include <math.h>
#include <stdint.h>

#define B_   8
#define SP_  800
#define SS_  48
#define NT_  848
#define DP_  2048
#define DS_  1024
#define DC_  1024
#define H_   8
#define HD_  256
#define FP_  16384
#define FS_  4096
#define EPS_ 1e-6f
#define MASKV_ (-2.3819763e+38f)

// ---------------- scratch (static device allocations) ----------------
__device__ float g_hp  [(size_t)B_*SP_*DP_];
__device__ float g_mod1[B_*3*DS_];
__device__ float g_mod2[B_*3*DS_];
__device__ float g_hs  [B_*SS_*DS_];
__device__ float g_q   [(size_t)B_*NT_*H_*HD_];
__device__ float g_k   [(size_t)B_*NT_*HD_];
__device__ float g_v   [(size_t)B_*NT_*HD_];
__device__ float g_sc  [(size_t)B_*H_*NT_*NT_];
__device__ float g_ao  [(size_t)B_*NT_*H_*HD_];
__device__ float g_resp[(size_t)B_*SP_*DP_];
__device__ float g_act [(size_t)B_*SP_*FP_];
__device__ float g_ress[B_*SS_*DS_];
__device__ float g_sact[B_*SS_*FS_];

// ---------------- helpers ----------------
__device__ __forceinline__ uint32_t smem_u32(const void* p) {
    uint32_t a;
    asm("{ .reg .u64 t; cvta.to.shared.u64 t, %1; cvt.u32.u64 %0, t; }" : "=r"(a) : "l"(p));
    return a;
}

__device__ __forceinline__ void ldm_x4(uint32_t& r0, uint32_t& r1, uint32_t& r2, uint32_t& r3,
                                       uint32_t addr) {
    asm volatile("ldmatrix.sync.aligned.m8n8.x4.shared.b16 {%0,%1,%2,%3}, [%4];"
                 : "=r"(r0), "=r"(r1), "=r"(r2), "=r"(r3) : "r"(addr));
}
__device__ __forceinline__ void ldm_x2(uint32_t& r0, uint32_t& r1, uint32_t addr) {
    asm volatile("ldmatrix.sync.aligned.m8n8.x2.shared.b16 {%0,%1}, [%2];"
                 : "=r"(r0), "=r"(r1) : "r"(addr));
}
__device__ __forceinline__ void mma_bf16(float* c, uint32_t a0, uint32_t a1, uint32_t a2,
                                         uint32_t a3, uint32_t b0, uint32_t b1) {
    asm volatile("mma.sync.aligned.m16n8k16.row.col.f32.bf16.bf16.f32 "
                 "{%0,%1,%2,%3}, {%4,%5,%6,%7}, {%8,%9}, {%0,%1,%2,%3};"
                 : "+f"(c[0]), "+f"(c[1]), "+f"(c[2]), "+f"(c[3])
                 : "r"(a0), "r"(a1), "r"(a2), "r"(a3), "r"(b0), "r"(b1));
}

__device__ __forceinline__ uint32_t pack_bf2(__nv_bfloat16 a, __nv_bfloat16 b) {
    return (uint32_t)__bfloat16_as_ushort(a) | ((uint32_t)__bfloat16_as_ushort(b) << 16);
}

__device__ __forceinline__ float gelu_tanh(float x) {
    float x3 = x * x * x;
    return 0.5f * x * (1.0f + tanhf(0.7978845608028654f * (x + 0.044715f * x3)));
}

// ---------------- GEMM params ----------------
struct GemmP {
    const float* A; const float* Bm; float* C;
    int M, N, K, lda, ldb, ldc;
    long long sA, sB, sC, sA2, sB2, sC2;
    int zdiv;
    int transB;
    int epi;       // 0 plain, 1 +bias, 2 gelu, 3 C*=acc, 4 +res, 5 res+acc*gate, 6 mask+scale
    float alpha;
    const float* bias;
    const float* res;  long long sRes;
    const float* gate; long long sGate; int rowsPerB; int ldGate;
};

// smem: tiles of 128 rows x 32 k, stride 40 bf16 (80 B = 5 x 16B -> conflict-free ldmatrix)
#define KSTRIDE_B 80                 // bytes per row
#define TILE_B    (128 * KSTRIDE_B)  // 10240
#define OFF_AH(s) ((s) * 4 * TILE_B + 0 * TILE_B)
#define OFF_AL(s) ((s) * 4 * TILE_B + 1 * TILE_B)
#define OFF_BH(s) ((s) * 4 * TILE_B + 2 * TILE_B)
#define OFF_BL(s) ((s) * 4 * TILE_B + 3 * TILE_B)
#define SMEM_TOTAL (8 * TILE_B)      // 81920

__device__ __forceinline__ void sts_hilo4(char* bh, char* bl, int row, int col, float4 v) {
    __nv_bfloat16 h0 = __float2bfloat16(v.x), h1 = __float2bfloat16(v.y);
    __nv_bfloat16 h2 = __float2bfloat16(v.z), h3 = __float2bfloat16(v.w);
    __nv_bfloat16 l0 = __float2bfloat16(v.x - __bfloat162float(h0));
    __nv_bfloat16 l1 = __float2bfloat16(v.y - __bfloat162float(h1));
    __nv_bfloat16 l2 = __float2bfloat16(v.z - __bfloat162float(h2));
    __nv_bfloat16 l3 = __float2bfloat16(v.w - __bfloat162float(h3));
    int byte = row * KSTRIDE_B + col * 2;
    *(uint32_t*)(bh + byte)     = pack_bf2(h0, h1);
    *(uint32_t*)(bh + byte + 4) = pack_bf2(h2, h3);
    *(uint32_t*)(bl + byte)     = pack_bf2(l0, l1);
    *(uint32_t*)(bl + byte + 4) = pack_bf2(l2, l3);
}

// ---------------- HMMA GEMM: 128x128 tile, 8 warps, bf16x3 split ----------------
__global__ void __launch_bounds__(256, 1) gemm_tc(GemmP p) {
    extern __shared__ char smem[];
    const uint32_t sb = smem_u32(smem);

    const int tid  = threadIdx.x;
    const int wid  = tid >> 5, lane = tid & 31;
    const int gid  = lane >> 2, tig = lane & 3;
    const int wr   = wid >> 2, wc = wid & 3;     // 2 x 4 warp grid

    const int z  = blockIdx.z;
    const int zb = z / p.zdiv, zr = z % p.zdiv;
    const float* A  = p.A  + (long long)zb * p.sA + (long long)zr * p.sA2;
    const float* Bm = p.Bm + (long long)zb * p.sB + (long long)zr * p.sB2;
    float*       C  = p.C  + (long long)zb * p.sC + (long long)zr * p.sC2;

    const int bm = blockIdx.y * 128;
    const int bn = blockIdx.x * 128;

    float acc[4][4][4];
#pragma unroll
    for (int i = 0; i < 4; i++)
#pragma unroll
        for (int j = 0; j < 4; j++)
#pragma unroll
            for (int r = 0; r < 4; r++) acc[i][j][r] = 0.f;

    const int nkt = (p.K + 31) >> 5;
    float4 ra[4], rb[4];

    // ldmatrix shared addresses (per-thread, fixed row/col pattern)
    const int a_row = wr * 64 + (lane & 15);
    const int a_col = (lane >> 4) * 8;
    const int b_row = wc * 32 + (lane & 7);
    const int b_col = ((lane >> 3) & 1) * 8;

#define LOAD_GMEM(kt_)                                                                  \
    do {                                                                                \
        const int kb = (kt_) << 5;                                                      \
        _Pragma("unroll")                                                               \
        for (int i = 0; i < 4; i++) {                                                   \
            int idx = tid + i * 256;                                                    \
            int row = idx >> 3, col = (idx & 7) << 2;                                   \
            int gm = bm + row, gk = kb + col;                                           \
            ra[i] = make_float4(0.f, 0.f, 0.f, 0.f);                                    \
            if (gm < p.M && gk < p.K)                                                   \
                ra[i] = *(const float4*)(A + (long long)gm * p.lda + gk);               \
        }                                                                               \
        if (!p.transB) {                                                                \
            _Pragma("unroll")                                                           \
            for (int i = 0; i < 4; i++) {                                               \
                int idx = tid + i * 256;                                                \
                int row = idx >> 3, col = (idx & 7) << 2;                               \
                int gn = bn + row, gk = kb + col;                                       \
                rb[i] = make_float4(0.f, 0.f, 0.f, 0.f);                                \
                if (gn < p.N && gk < p.K)                                               \
                    rb[i] = *(const float4*)(Bm + (long long)gn * p.ldb + gk);          \
            }                                                                           \
        } else {                                                                        \
            _Pragma("unroll")                                                           \
            for (int i = 0; i < 4; i++) {                                               \
                int idx = tid + i * 256;                                                \
                int k = idx >> 5, n4 = (idx & 31) << 2;                                 \
                int gk = kb + k, gn = bn + n4;                                          \
                rb[i] = make_float4(0.f, 0.f, 0.f, 0.f);                                \
                if (gk < p.K && gn < p.N)                                               \
                    rb[i] = *(const float4*)(Bm + (long long)gk * p.ldb + gn);          \
            }                                                                           \
        }                                                                               \
    } while (0)

#define STORE_SMEM(s_)                                                                  \
    do {                                                                                \
        char* ah = smem + OFF_AH(s_); char* al = smem + OFF_AL(s_);                     \
        char* bh = smem + OFF_BH(s_); char* bl = smem + OFF_BL(s_);                     \
        _Pragma("unroll")                                                               \
        for (int i = 0; i < 4; i++) {                                                   \
            int idx = tid + i * 256;                                                    \
            int row = idx >> 3, col = (idx & 7) << 2;                                   \
            sts_hilo4(ah, al, row, col, ra[i]);                                         \
        }                                                                               \
        if (!p.transB) {                                                                \
            _Pragma("unroll")                                                           \
            for (int i = 0; i < 4; i++) {                                               \
                int idx = tid + i * 256;                                                \
                int row = idx >> 3, col = (idx & 7) << 2;                               \
                sts_hilo4(bh, bl, row, col, rb[i]);                                     \
            }                                                                           \
        } else {                                                                        \
            _Pragma("unroll")                                                           \
            for (int i = 0; i < 4; i++) {                                               \
                int idx = tid + i * 256;                                                \
                int k = idx >> 5, n4 = (idx & 31) << 2;                                 \
                float vv[4] = {rb[i].x, rb[i].y, rb[i].z, rb[i].w};                     \
                _Pragma("unroll")                                                       \
                for (int j = 0; j < 4; j++) {                                           \
                    __nv_bfloat16 h = __float2bfloat16(vv[j]);                          \
                    __nv_bfloat16 l = __float2bfloat16(vv[j] - __bfloat162float(h));    \
                    int byte = (n4 + j) * KSTRIDE_B + k * 2;                            \
                    *(unsigned short*)(bh + byte) = __bfloat16_as_ushort(h);            \
                    *(unsigned short*)(bl + byte) = __bfloat16_as_ushort(l);            \
                }                                                                       \
            }                                                                           \
        }                                                                               \
    } while (0)

    LOAD_GMEM(0);
    STORE_SMEM(0);
    __syncthreads();

    for (int kt = 0; kt < nkt; kt++) {
        const int s = kt & 1;
        if (kt + 1 < nkt) LOAD_GMEM(kt + 1);

        const uint32_t sAh = sb + OFF_AH(s), sAl = sb + OFF_AL(s);
        const uint32_t sBh = sb + OFF_BH(s), sBl = sb + OFF_BL(s);
#pragma unroll
        for (int k16 = 0; k16 < 2; k16++) {
            uint32_t bh[4][2], bl[4][2];
#pragma unroll
            for (int nn = 0; nn < 4; nn++) {
                uint32_t off = (uint32_t)((b_row + nn * 8) * KSTRIDE_B + (b_col + k16 * 16) * 2);
                ldm_x2(bh[nn][0], bh[nn][1], sBh + off);
                ldm_x2(bl[nn][0], bl[nn][1], sBl + off);
            }
#pragma unroll
            for (int mm = 0; mm < 4; mm++) {
                uint32_t off = (uint32_t)((a_row + mm * 16) * KSTRIDE_B + (a_col + k16 * 16) * 2);
                uint32_t ah0, ah1, ah2, ah3, al0, al1, al2, al3;
                ldm_x4(ah0, ah1, ah2, ah3, sAh + off);
                ldm_x4(al0, al1, al2, al3, sAl + off);
#pragma unroll
                for (int nn = 0; nn < 4; nn++) {
                    mma_bf16(acc[mm][nn], ah0, ah1, ah2, ah3, bh[nn][0], bh[nn][1]);
                    mma_bf16(acc[mm][nn], al0, al1, al2, al3, bh[nn][0], bh[nn][1]);
                    mma_bf16(acc[mm][nn], ah0, ah1, ah2, ah3, bl[nn][0], bl[nn][1]);
                }
            }
        }
        __syncthreads();
        if (kt + 1 < nkt) {
            STORE_SMEM((kt + 1) & 1);
            __syncthreads();
        }
    }

    // ---------------- epilogue ----------------
#pragma unroll
    for (int mm = 0; mm < 4; mm++) {
#pragma unroll
        for (int rr = 0; rr < 2; rr++) {
            int m = bm + wr * 64 + mm * 16 + gid + rr * 8;
            if (m >= p.M) continue;
#pragma unroll
            for (int nn = 0; nn < 4; nn++) {
#pragma unroll
                for (int cc = 0; cc < 2; cc++) {
                    int n = bn + wc * 32 + nn * 8 + tig * 2 + cc;
                    if (n >= p.N) continue;
                    float v = acc[mm][nn][rr * 2 + cc] * p.alpha;
                    long long cidx = (long long)m * p.ldc + n;
                    switch (p.epi) {
                        case 1: v += p.bias[n]; break;
                        case 2: v = gelu_tanh(v); break;
                        case 3: v = C[cidx] * v; break;
                        case 4: v += p.res[(long long)zb * p.sRes + cidx]; break;
                        case 5: v = p.res[(long long)zb * p.sRes + cidx]
                                    + v * p.gate[(long long)zb * p.sGate
                                                 + (long long)(m / p.rowsPerB) * p.ldGate + n];
                                break;
                        case 6: if (m < SP_ && n >= SP_) v += MASKV_; break;
                        default: break;
                    }
                    C[cidx] = v;
                }
            }
        }
    }
}

// ---------------- RMS norms ----------------
__global__ __launch_bounds__(256) void rmsnorm_gemma_kernel(
    const float* __restrict__ x, const float* __restrict__ w,
    float* __restrict__ out, int D)
{
    long long row = blockIdx.x;
    const float* xr = x + row * D;
    float* orow = out + row * D;
    float ss = 0.f;
    for (int i = threadIdx.x; i < D; i += 256) { float v = xr[i]; ss = fmaf(v, v, ss); }
    __shared__ float sh[32];
    int lane = threadIdx.x & 31, wid = threadIdx.x >> 5;
#pragma unroll
    for (int o = 16; o > 0; o >>= 1) ss += __shfl_down_sync(0xffffffffu, ss, o);
    if (lane == 0) sh[wid] = ss;
    __syncthreads();
    if (threadIdx.x == 0) {
        float t = 0.f;
        for (int i = 0; i < 8; i++) t += sh[i];
        sh[0] = rsqrtf(t / (float)D + EPS_);
    }
    __syncthreads();
    float r = sh[0];
    for (int i = threadIdx.x; i < D; i += 256) orow[i] = xr[i] * r * (1.0f + w[i]);
}

__global__ __launch_bounds__(256) void ada_norm_kernel(
    const float* __restrict__ x, const float* __restrict__ mod, float* __restrict__ out)
{
    int row = blockIdx.x;
    int b = row / SS_;
    const float* xr = x + (long long)row * DS_;
    const float* mrow = mod + (long long)b * 3 * DS_;
    float* orow = out + (long long)row * DS_;
    float ss = 0.f;
    for (int i = threadIdx.x; i < DS_; i += 256) { float v = xr[i]; ss = fmaf(v, v, ss); }
    __shared__ float sh[32];
    int lane = threadIdx.x & 31, wid = threadIdx.x >> 5;
#pragma unroll
    for (int o = 16; o > 0; o >>= 1) ss += __shfl_down_sync(0xffffffffu, ss, o);
    if (lane == 0) sh[wid] = ss;
    __syncthreads();
    if (threadIdx.x == 0) {
        float t = 0.f;
        for (int i = 0; i < 8; i++) t += sh[i];
        sh[0] = rsqrtf(t / (float)DS_ + EPS_);
    }
    __syncthreads();
    float r = sh[0];
    for (int i = threadIdx.x; i < DS_; i += 256)
        orow[i] = xr[i] * r * (1.0f + mrow[i]) + mrow[DS_ + i];
}

// ---------------- RoPE ----------------
__global__ void rope_kernel(float* __restrict__ q, float* __restrict__ k) {
    long long idx = (long long)blockIdx.x * blockDim.x + threadIdx.x;
    const long long NQ = (long long)B_ * NT_ * H_ * (HD_ / 2);
    const long long NK = (long long)B_ * NT_ * (HD_ / 2);
    const float LN_TH_OVER = 9.210340371976184f / 128.0f;
    if (idx < NQ) {
        int d = (int)(idx & 127); long long t = idx >> 7;
        int h = (int)(t % H_); t /= H_;
        int s = (int)(t % NT_); int b = (int)(t / NT_);
        float inv = expf(-(float)d * LN_TH_OVER);
        float ang = (float)s * inv;
        float c, sn; sincosf(ang, &sn, &c);
        float* pq = q + ((long long)(b * NT_ + s)) * (H_ * HD_) + h * HD_;
        float x1 = pq[d], x2 = pq[d + 128];
        pq[d]       = x1 * c - x2 * sn;
        pq[d + 128] = x2 * c + x1 * sn;
    } else if (idx < NQ + NK) {
        long long r = idx - NQ;
        int d = (int)(r & 127); long long t = r >> 7;
        int s = (int)(t % NT_); int b = (int)(t / NT_);
        float inv = expf(-(float)d * LN_TH_OVER);
        float ang = (float)s * inv;
        float c, sn; sincosf(ang, &sn, &c);
        float* pk = k + ((long long)(b * NT_ + s)) * HD_;
        float x1 = pk[d], x2 = pk[d + 128];
        pk[d]       = x1 * c - x2 * sn;
        pk[d + 128] = x2 * c + x1 * sn;
    }
}

// ---------------- softmax ----------------
__global__ __launch_bounds__(256) void softmax_kernel(float* __restrict__ sc) {
    long long row = blockIdx.x;
    float* p = sc + row * NT_;
    __shared__ float sh[32];
    int lane = threadIdx.x & 31, wid = threadIdx.x >> 5;

    float mx = -3.4e38f;
    for (int i = threadIdx.x; i < NT_; i += 256) mx = fmaxf(mx, p[i]);
#pragma unroll
    for (int o = 16; o > 0; o >>= 1) mx = fmaxf(mx, __shfl_down_sync(0xffffffffu, mx, o));
    if (lane == 0) sh[wid] = mx;
    __syncthreads();
    if (threadIdx.x == 0) {
        float t = -3.4e38f;
        for (int i = 0; i < 8; i++) t = fmaxf(t, sh[i]);
        sh[0] = t;
    }
    __syncthreads();
    mx = sh[0];
    __syncthreads();

    float sm = 0.f;
    for (int i = threadIdx.x; i < NT_; i += 256) {
        float e = expf(p[i] - mx);
        p[i] = e;
        sm += e;
    }
#pragma unroll
    for (int o = 16; o > 0; o >>= 1) sm += __shfl_down_sync(0xffffffffu, sm, o);
    if (lane == 0) sh[wid] = sm;
    __syncthreads();
    if (threadIdx.x == 0) {
        float t = 0.f;
        for (int i = 0; i < 8; i++) t += sh[i];
        sh[0] = 1.0f / t;
    }
    __syncthreads();
    float inv = sh[0];
    for (int i = threadIdx.x; i < NT_; i += 256) p[i] *= inv;
}

// ---------------- host side ----------------
static GemmP gp(const float* A, const float* Bm, float* C,
                int M, int N, int K, int lda, int ldb, int ldc) {
    GemmP p = {};
    p.A = A; p.Bm = Bm; p.C = C;
    p.M = M; p.N = N; p.K = K; p.lda = lda; p.ldb = ldb; p.ldc = ldc;
    p.zdiv = 1; p.alpha = 1.0f; p.rowsPerB = 1 << 30;
    return p;
}

static void launch_gemm(const GemmP& p, int batch) {
    dim3 grid((p.N + 127) / 128, (p.M + 127) / 128, batch);
    gemm_tc<<<grid, 256, SMEM_TOTAL>>>(p);
}

extern "C" void kernel_launch(void* const* d_in, const int* in_sizes, int n_in,
                              void* d_out, int out_size) {
    const float* prefix_x    = (const float*)d_in[0];
    const float* suffix_x    = (const float*)d_in[1];
    const float* cond        = (const float*)d_in[2];
    const float* p_ln_w      = (const float*)d_in[3];
    const float* p_q_w       = (const float*)d_in[4];
    const float* p_k_w       = (const float*)d_in[5];
    const float* p_v_w       = (const float*)d_in[6];
    const float* p_o_w       = (const float*)d_in[7];
    const float* p_post_ln_w = (const float*)d_in[8];
    const float* p_gate_w    = (const float*)d_in[9];
    const float* p_up_w      = (const float*)d_in[10];
    const float* p_down_w    = (const float*)d_in[11];
    const float* s_ada1_w    = (const float*)d_in[12];
    const float* s_ada1_b    = (const float*)d_in[13];
    const float* s_q_w       = (const float*)d_in[14];
    const float* s_k_w       = (const float*)d_in[15];
    const float* s_v_w       = (const float*)d_in[16];
    const float* s_o_w       = (const float*)d_in[17];
    const float* s_ada2_w    = (const float*)d_in[18];
    const float* s_ada2_b    = (const float*)d_in[19];
    const float* s_gate_w    = (const float*)d_in[20];
    const float* s_up_w      = (const float*)d_in[21];
    const float* s_down_w    = (const float*)d_in[22];
    float* out = (float*)d_out;

    cudaFuncSetAttribute(gemm_tc, cudaFuncAttributeMaxDynamicSharedMemorySize, SMEM_TOTAL);

    float *hp, *mod1, *mod2, *hs, *q, *k, *v, *sc, *ao, *resp, *act, *ress, *sact;
    cudaGetSymbolAddress((void**)&hp,   g_hp);
    cudaGetSymbolAddress((void**)&mod1, g_mod1);
    cudaGetSymbolAddress((void**)&mod2, g_mod2);
    cudaGetSymbolAddress((void**)&hs,   g_hs);
    cudaGetSymbolAddress((void**)&q,    g_q);
    cudaGetSymbolAddress((void**)&k,    g_k);
    cudaGetSymbolAddress((void**)&v,    g_v);
    cudaGetSymbolAddress((void**)&sc,   g_sc);
    cudaGetSymbolAddress((void**)&ao,   g_ao);
    cudaGetSymbolAddress((void**)&resp, g_resp);
    cudaGetSymbolAddress((void**)&act,  g_act);
    cudaGetSymbolAddress((void**)&ress, g_ress);
    cudaGetSymbolAddress((void**)&sact, g_sact);

    // 1. prefix gemma norm
    rmsnorm_gemma_kernel<<<B_ * SP_, 256>>>(prefix_x, p_ln_w, hp, DP_);

    // 2. adaLN modulation vectors
    {
        GemmP p = gp(cond, s_ada1_w, mod1, B_, 3 * DS_, DC_, DC_, DC_, 3 * DS_);
        p.epi = 1; p.bias = s_ada1_b;
        launch_gemm(p, 1);
        GemmP p2 = gp(cond, s_ada2_w, mod2, B_, 3 * DS_, DC_, DC_, DC_, 3 * DS_);
        p2.epi = 1; p2.bias = s_ada2_b;
        launch_gemm(p2, 1);
    }

    // 3. suffix adaLN #1
    ada_norm_kernel<<<B_ * SS_, 256>>>(suffix_x, mod1, hs);

    // 4. QKV projections
    {
        GemmP p = gp(hp, p_q_w, q, SP_, H_ * HD_, DP_, DP_, DP_, H_ * HD_);
        p.sA = (long long)SP_ * DP_; p.sC = (long long)NT_ * H_ * HD_;
        launch_gemm(p, B_);
    }
    {
        GemmP p = gp(hs, s_q_w, q + (long long)SP_ * H_ * HD_, SS_, H_ * HD_, DS_, DS_, DS_, H_ * HD_);
        p.sA = (long long)SS_ * DS_; p.sC = (long long)NT_ * H_ * HD_;
        launch_gemm(p, B_);
    }
    {
        GemmP p = gp(hp, p_k_w, k, SP_, HD_, DP_, DP_, DP_, HD_);
        p.sA = (long long)SP_ * DP_; p.sC = (long long)NT_ * HD_;
        launch_gemm(p, B_);
    }
    {
        GemmP p = gp(hs, s_k_w, k + (long long)SP_ * HD_, SS_, HD_, DS_, DS_, DS_, HD_);
        p.sA = (long long)SS_ * DS_; p.sC = (long long)NT_ * HD_;
        launch_gemm(p, B_);
    }
    {
        GemmP p = gp(hp, p_v_w, v, SP_, HD_, DP_, DP_, DP_, HD_);
        p.sA = (long long)SP_ * DP_; p.sC = (long long)NT_ * HD_;
        launch_gemm(p, B_);
    }
    {
        GemmP p = gp(hs, s_v_w, v + (long long)SP_ * HD_, SS_, HD_, DS_, DS_, DS_, HD_);
        p.sA = (long long)SS_ * DS_; p.sC = (long long)NT_ * HD_;
        launch_gemm(p, B_);
    }

    // 5. RoPE
    {
        long long total = (long long)B_ * NT_ * H_ * (HD_ / 2) + (long long)B_ * NT_ * (HD_ / 2);
        int blocks = (int)((total + 255) / 256);
        rope_kernel<<<blocks, 256>>>(q, k);
    }

    // 6. scores = QK^T/16 + mask
    {
        GemmP p = gp(q, k, sc, NT_, NT_, HD_, H_ * HD_, HD_, NT_);
        p.zdiv = H_;
        p.sA = (long long)NT_ * H_ * HD_; p.sA2 = HD_;
        p.sB = (long long)NT_ * HD_;      p.sB2 = 0;
        p.sC = (long long)H_ * NT_ * NT_; p.sC2 = (long long)NT_ * NT_;
        p.epi = 6; p.alpha = 0.0625f;
        launch_gemm(p, B_ * H_);
    }

    // 7. softmax
    softmax_kernel<<<B_ * H_ * NT_, 256>>>(sc);

    // 8. attn @ V
    {
        GemmP p = gp(sc, v, ao, NT_, HD_, NT_, NT_, HD_, H_ * HD_);
        p.zdiv = H_; p.transB = 1;
        p.sA = (long long)H_ * NT_ * NT_; p.sA2 = (long long)NT_ * NT_;
        p.sB = (long long)NT_ * HD_;      p.sB2 = 0;
        p.sC = (long long)NT_ * H_ * HD_; p.sC2 = HD_;
        launch_gemm(p, B_ * H_);
    }

    // 9. prefix O-proj + residual
    {
        GemmP p = gp(ao, p_o_w, resp, SP_, DP_, H_ * HD_, H_ * HD_, H_ * HD_, DP_);
        p.sA = (long long)NT_ * H_ * HD_; p.sC = (long long)SP_ * DP_;
        p.epi = 4; p.res = prefix_x; p.sRes = (long long)SP_ * DP_;
        launch_gemm(p, B_);
    }

    // 10. post-norm
    rmsnorm_gemma_kernel<<<B_ * SP_, 256>>>(resp, p_post_ln_w, hp, DP_);

    // 11-13. prefix MLP
    {
        GemmP p = gp(hp, p_gate_w, act, B_ * SP_, FP_, DP_, DP_, DP_, FP_);
        p.epi = 2;
        launch_gemm(p, 1);
    }
    {
        GemmP p = gp(hp, p_up_w, act, B_ * SP_, FP_, DP_, DP_, DP_, FP_);
        p.epi = 3;
        launch_gemm(p, 1);
    }
    {
        GemmP p = gp(act, p_down_w, out, B_ * SP_, DP_, FP_, FP_, FP_, DP_);
        p.epi = 4; p.res = resp; p.sRes = 0;
        launch_gemm(p, 1);
    }

    // 14. suffix O-proj with gate
    {
        GemmP p = gp(ao + (long long)SP_ * H_ * HD_, s_o_w, ress, SS_, DS_, H_ * HD_, H_ * HD_, H_ * HD_, DS_);
        p.sA = (long long)NT_ * H_ * HD_; p.sC = (long long)SS_ * DS_;
        p.epi = 5; p.res = suffix_x; p.sRes = (long long)SS_ * DS_;
        p.gate = mod1 + 2 * DS_; p.sGate = 3 * DS_; p.rowsPerB = 1 << 30; p.ldGate = 0;
        launch_gemm(p, B_);
    }

    // 15. suffix adaLN #2
    ada_norm_kernel<<<B_ * SS_, 256>>>(ress, mod2, hs);

    // 16-18. suffix MLP with gate2
    {
        GemmP p = gp(hs, s_gate_w, sact, B_ * SS_, FS_, DS_, DS_, DS_, FS_);
        p.epi = 2;
        launch_gemm(p, 1);
    }
    {
        GemmP p = gp(hs, s_up_w, sact, B_ * SS_, FS_, DS_, DS_, DS_, FS_);
        p.epi = 3;
        launch_gemm(p, 1);
    }
    {
        GemmP p = gp(sact, s_down_w, out + (long long)B_ * SP_ * DP_, B_ * SS_, DS_, FS_, FS_, FS_, DS_);
        p.epi = 5; p.res = ress; p.sRes = 0;
        p.gate = mod2 + 2 * DS_; p.sGate = 0; p.rowsPerB = SS_; p.ldGate = 3 * DS_;
        launch_gemm(p, 1);
    }
}

// round 13
// speedup vs baseline: 2.5710x; 1.2906x over previous
#include <cuda_runtime.h>
#include <cuda_bf16.h>
#include <math.h>
#include <stdint.h>

#define B_   8
#define SP_  800
#define SS_  48
#define NT_  848
#define DP_  2048
#define DS_  1024
#define DC_  1024
#define H_   8
#define HD_  256
#define FP_  16384
#define FS_  4096
#define EPS_ 1e-6f
#define MASKV_ (-2.3819763e+38f)

// ---------------- scratch (static device allocations) ----------------
__device__ float g_hp  [(size_t)B_*SP_*DP_];
__device__ float g_mod1[B_*3*DS_];
__device__ float g_mod2[B_*3*DS_];
__device__ float g_hs  [B_*SS_*DS_];
__device__ float g_q   [(size_t)B_*NT_*H_*HD_];
__device__ float g_k   [(size_t)B_*NT_*HD_];
__device__ float g_v   [(size_t)B_*NT_*HD_];
__device__ float g_sc  [(size_t)B_*H_*NT_*NT_];
__device__ float g_ao  [(size_t)B_*NT_*H_*HD_];
__device__ float g_resp[(size_t)B_*SP_*DP_];
__device__ float g_act [(size_t)B_*SP_*FP_];
__device__ float g_ress[B_*SS_*DS_];
__device__ float g_sact[B_*SS_*FS_];

// ---------------- helpers ----------------
__device__ __forceinline__ uint32_t smem_u32(const void* p) {
    uint32_t a;
    asm("{ .reg .u64 t; cvta.to.shared.u64 t, %1; cvt.u32.u64 %0, t; }" : "=r"(a) : "l"(p));
    return a;
}

__device__ __forceinline__ void ldm_x4(uint32_t& r0, uint32_t& r1, uint32_t& r2, uint32_t& r3,
                                       uint32_t addr) {
    asm volatile("ldmatrix.sync.aligned.m8n8.x4.shared.b16 {%0,%1,%2,%3}, [%4];"
                 : "=r"(r0), "=r"(r1), "=r"(r2), "=r"(r3) : "r"(addr));
}
__device__ __forceinline__ void ldm_x2(uint32_t& r0, uint32_t& r1, uint32_t addr) {
    asm volatile("ldmatrix.sync.aligned.m8n8.x2.shared.b16 {%0,%1}, [%2];"
                 : "=r"(r0), "=r"(r1) : "r"(addr));
}
__device__ __forceinline__ void mma_bf16(float* c, uint32_t a0, uint32_t a1, uint32_t a2,
                                         uint32_t a3, uint32_t b0, uint32_t b1) {
    asm volatile("mma.sync.aligned.m16n8k16.row.col.f32.bf16.bf16.f32 "
                 "{%0,%1,%2,%3}, {%4,%5,%6,%7}, {%8,%9}, {%0,%1,%2,%3};"
                 : "+f"(c[0]), "+f"(c[1]), "+f"(c[2]), "+f"(c[3])
                 : "r"(a0), "r"(a1), "r"(a2), "r"(a3), "r"(b0), "r"(b1));
}

__device__ __forceinline__ uint32_t pack_bf2(__nv_bfloat16 a, __nv_bfloat16 b) {
    return (uint32_t)__bfloat16_as_ushort(a) | ((uint32_t)__bfloat16_as_ushort(b) << 16);
}

__device__ __forceinline__ float gelu_tanh(float x) {
    float x3 = x * x * x;
    return 0.5f * x * (1.0f + tanhf(0.7978845608028654f * (x + 0.044715f * x3)));
}

// ---------------- GEMM params ----------------
struct GemmP {
    const float* A; const float* Bm; float* C;
    int M, N, K, lda, ldb, ldc;
    long long sA, sB, sC, sA2, sB2, sC2;
    int zdiv;
    int transB;
    int epi;       // 0 plain, 1 +bias, 2 gelu, 3 C*=acc, 4 +res, 5 res+acc*gate, 6 mask+scale
    float alpha;
    const float* bias;
    const float* res;  long long sRes;
    const float* gate; long long sGate; int rowsPerB; int ldGate;
};

// smem: tiles of 128 rows x 32 k, stride 40 bf16 (80 B = 5 x 16B -> conflict-free ldmatrix)
#define KSTRIDE_B 80                 // bytes per row
#define TILE_B    (128 * KSTRIDE_B)  // 10240
#define OFF_AH(s) ((s) * 4 * TILE_B + 0 * TILE_B)
#define OFF_AL(s) ((s) * 4 * TILE_B + 1 * TILE_B)
#define OFF_BH(s) ((s) * 4 * TILE_B + 2 * TILE_B)
#define OFF_BL(s) ((s) * 4 * TILE_B + 3 * TILE_B)
#define SMEM_TOTAL (8 * TILE_B)      // 81920

__device__ __forceinline__ void sts_hilo4(char* bh, char* bl, int row, int col, float4 v) {
    __nv_bfloat16 h0 = __float2bfloat16(v.x), h1 = __float2bfloat16(v.y);
    __nv_bfloat16 h2 = __float2bfloat16(v.z), h3 = __float2bfloat16(v.w);
    __nv_bfloat16 l0 = __float2bfloat16(v.x - __bfloat162float(h0));
    __nv_bfloat16 l1 = __float2bfloat16(v.y - __bfloat162float(h1));
    __nv_bfloat16 l2 = __float2bfloat16(v.z - __bfloat162float(h2));
    __nv_bfloat16 l3 = __float2bfloat16(v.w - __bfloat162float(h3));
    int byte = row * KSTRIDE_B + col * 2;
    *(uint32_t*)(bh + byte)     = pack_bf2(h0, h1);
    *(uint32_t*)(bh + byte + 4) = pack_bf2(h2, h3);
    *(uint32_t*)(bl + byte)     = pack_bf2(l0, l1);
    *(uint32_t*)(bl + byte + 4) = pack_bf2(l2, l3);
}

// ---------------- HMMA GEMM: 128x128 tile, 8 warps, bf16x3 split, 2 CTAs/SM ----------------
__global__ void __launch_bounds__(256, 2) gemm_tc(GemmP p) {
    extern __shared__ char smem[];
    const uint32_t sb = smem_u32(smem);

    const int tid  = threadIdx.x;
    const int wid  = tid >> 5, lane = tid & 31;
    const int gid  = lane >> 2, tig = lane & 3;
    const int wr   = wid >> 2, wc = wid & 3;     // 2 x 4 warp grid

    const int z  = blockIdx.z;
    const int zb = z / p.zdiv, zr = z % p.zdiv;
    const float* A  = p.A  + (long long)zb * p.sA + (long long)zr * p.sA2;
    const float* Bm = p.Bm + (long long)zb * p.sB + (long long)zr * p.sB2;
    float*       C  = p.C  + (long long)zb * p.sC + (long long)zr * p.sC2;

    const int bm = blockIdx.y * 128;
    const int bn = blockIdx.x * 128;

    float acc[4][4][4];
#pragma unroll
    for (int i = 0; i < 4; i++)
#pragma unroll
        for (int j = 0; j < 4; j++)
#pragma unroll
            for (int r = 0; r < 4; r++) acc[i][j][r] = 0.f;

    const int nkt = (p.K + 31) >> 5;
    float4 ra[4], rb[4];

    // ldmatrix shared addresses (per-thread, fixed row/col pattern)
    const int a_row = wr * 64 + (lane & 15);
    const int a_col = (lane >> 4) * 8;
    const int b_row = wc * 32 + (lane & 7);
    const int b_col = ((lane >> 3) & 1) * 8;

#define LOAD_GMEM(kt_)                                                                  \
    do {                                                                                \
        const int kb = (kt_) << 5;                                                      \
        _Pragma("unroll")                                                               \
        for (int i = 0; i < 4; i++) {                                                   \
            int idx = tid + i * 256;                                                    \
            int row = idx >> 3, col = (idx & 7) << 2;                                   \
            int gm = bm + row, gk = kb + col;                                           \
            ra[i] = make_float4(0.f, 0.f, 0.f, 0.f);                                    \
            if (gm < p.M && gk < p.K)                                                   \
                ra[i] = *(const float4*)(A + (long long)gm * p.lda + gk);               \
        }                                                                               \
        if (!p.transB) {                                                                \
            _Pragma("unroll")                                                           \
            for (int i = 0; i < 4; i++) {                                               \
                int idx = tid + i * 256;                                                \
                int row = idx >> 3, col = (idx & 7) << 2;                               \
                int gn = bn + row, gk = kb + col;                                       \
                rb[i] = make_float4(0.f, 0.f, 0.f, 0.f);                                \
                if (gn < p.N && gk < p.K)                                               \
                    rb[i] = *(const float4*)(Bm + (long long)gn * p.ldb + gk);          \
            }                                                                           \
        } else {                                                                        \
            _Pragma("unroll")                                                           \
            for (int i = 0; i < 4; i++) {                                               \
                int idx = tid + i * 256;                                                \
                int k = idx >> 5, n4 = (idx & 31) << 2;                                 \
                int gk = kb + k, gn = bn + n4;                                          \
                rb[i] = make_float4(0.f, 0.f, 0.f, 0.f);                                \
                if (gk < p.K && gn < p.N)                                               \
                    rb[i] = *(const float4*)(Bm + (long long)gk * p.ldb + gn);          \
            }                                                                           \
        }                                                                               \
    } while (0)

#define STORE_SMEM(s_)                                                                  \
    do {                                                                                \
        char* ah = smem + OFF_AH(s_); char* al = smem + OFF_AL(s_);                     \
        char* bh = smem + OFF_BH(s_); char* bl = smem + OFF_BL(s_);                     \
        _Pragma("unroll")                                                               \
        for (int i = 0; i < 4; i++) {                                                   \
            int idx = tid + i * 256;                                                    \
            int row = idx >> 3, col = (idx & 7) << 2;                                   \
            sts_hilo4(ah, al, row, col, ra[i]);                                         \
        }                                                                               \
        if (!p.transB) {                                                                \
            _Pragma("unroll")                                                           \
            for (int i = 0; i < 4; i++) {                                               \
                int idx = tid + i * 256;                                                \
                int row = idx >> 3, col = (idx & 7) << 2;                               \
                sts_hilo4(bh, bl, row, col, rb[i]);                                     \
            }                                                                           \
        } else {                                                                        \
            _Pragma("unroll")                                                           \
            for (int i = 0; i < 4; i++) {                                               \
                int idx = tid + i * 256;                                                \
                int k = idx >> 5, n4 = (idx & 31) << 2;                                 \
                float vv[4] = {rb[i].x, rb[i].y, rb[i].z, rb[i].w};                     \
                _Pragma("unroll")                                                       \
                for (int j = 0; j < 4; j++) {                                           \
                    __nv_bfloat16 h = __float2bfloat16(vv[j]);                          \
                    __nv_bfloat16 l = __float2bfloat16(vv[j] - __bfloat162float(h));    \
                    int byte = (n4 + j) * KSTRIDE_B + k * 2;                            \
                    *(unsigned short*)(bh + byte) = __bfloat16_as_ushort(h);            \
                    *(unsigned short*)(bl + byte) = __bfloat16_as_ushort(l);            \
                }                                                                       \
            }                                                                           \
        }                                                                               \
    } while (0)

    LOAD_GMEM(0);
    STORE_SMEM(0);
    __syncthreads();

    // Single-sync double-buffered mainloop:
    //   iter kt: LOAD(kt+1) -> MMA(buf s) -> STORE(buf 1-s) -> sync
    // Entering iter kt: buf s fully written (stored in kt-1 before its sync);
    // buf 1-s's readers (MMA of kt-1) finished before that same sync.
    for (int kt = 0; kt < nkt; kt++) {
        const int s = kt & 1;
        const bool more = (kt + 1 < nkt);
        if (more) LOAD_GMEM(kt + 1);

        const uint32_t sAh = sb + OFF_AH(s), sAl = sb + OFF_AL(s);
        const uint32_t sBh = sb + OFF_BH(s), sBl = sb + OFF_BL(s);
#pragma unroll
        for (int k16 = 0; k16 < 2; k16++) {
            uint32_t bh[4][2], bl[4][2];
#pragma unroll
            for (int nn = 0; nn < 4; nn++) {
                uint32_t off = (uint32_t)((b_row + nn * 8) * KSTRIDE_B + (b_col + k16 * 16) * 2);
                ldm_x2(bh[nn][0], bh[nn][1], sBh + off);
                ldm_x2(bl[nn][0], bl[nn][1], sBl + off);
            }
#pragma unroll
            for (int mm = 0; mm < 4; mm++) {
                uint32_t off = (uint32_t)((a_row + mm * 16) * KSTRIDE_B + (a_col + k16 * 16) * 2);
                uint32_t ah0, ah1, ah2, ah3, al0, al1, al2, al3;
                ldm_x4(ah0, ah1, ah2, ah3, sAh + off);
                ldm_x4(al0, al1, al2, al3, sAl + off);
#pragma unroll
                for (int nn = 0; nn < 4; nn++) {
                    mma_bf16(acc[mm][nn], ah0, ah1, ah2, ah3, bh[nn][0], bh[nn][1]);
                    mma_bf16(acc[mm][nn], al0, al1, al2, al3, bh[nn][0], bh[nn][1]);
                    mma_bf16(acc[mm][nn], ah0, ah1, ah2, ah3, bl[nn][0], bl[nn][1]);
                }
            }
        }
        if (more) STORE_SMEM(1 - s);
        __syncthreads();
    }

    // ---------------- epilogue ----------------
#pragma unroll
    for (int mm = 0; mm < 4; mm++) {
#pragma unroll
        for (int rr = 0; rr < 2; rr++) {
            int m = bm + wr * 64 + mm * 16 + gid + rr * 8;
            if (m >= p.M) continue;
#pragma unroll
            for (int nn = 0; nn < 4; nn++) {
#pragma unroll
                for (int cc = 0; cc < 2; cc++) {
                    int n = bn + wc * 32 + nn * 8 + tig * 2 + cc;
                    if (n >= p.N) continue;
                    float v = acc[mm][nn][rr * 2 + cc] * p.alpha;
                    long long cidx = (long long)m * p.ldc + n;
                    switch (p.epi) {
                        case 1: v += p.bias[n]; break;
                        case 2: v = gelu_tanh(v); break;
                        case 3: v = C[cidx] * v; break;
                        case 4: v += p.res[(long long)zb * p.sRes + cidx]; break;
                        case 5: v = p.res[(long long)zb * p.sRes + cidx]
                                    + v * p.gate[(long long)zb * p.sGate
                                                 + (long long)(m / p.rowsPerB) * p.ldGate + n];
                                break;
                        case 6: if (m < SP_ && n >= SP_) v += MASKV_; break;
                        default: break;
                    }
                    C[cidx] = v;
                }
            }
        }
    }
}

// ---------------- RMS norms ----------------
__global__ __launch_bounds__(256) void rmsnorm_gemma_kernel(
    const float* __restrict__ x, const float* __restrict__ w,
    float* __restrict__ out, int D)
{
    long long row = blockIdx.x;
    const float* xr = x + row * D;
    float* orow = out + row * D;
    float ss = 0.f;
    for (int i = threadIdx.x; i < D; i += 256) { float v = xr[i]; ss = fmaf(v, v, ss); }
    __shared__ float sh[32];
    int lane = threadIdx.x & 31, wid = threadIdx.x >> 5;
#pragma unroll
    for (int o = 16; o > 0; o >>= 1) ss += __shfl_down_sync(0xffffffffu, ss, o);
    if (lane == 0) sh[wid] = ss;
    __syncthreads();
    if (threadIdx.x == 0) {
        float t = 0.f;
        for (int i = 0; i < 8; i++) t += sh[i];
        sh[0] = rsqrtf(t / (float)D + EPS_);
    }
    __syncthreads();
    float r = sh[0];
    for (int i = threadIdx.x; i < D; i += 256) orow[i] = xr[i] * r * (1.0f + w[i]);
}

__global__ __launch_bounds__(256) void ada_norm_kernel(
    const float* __restrict__ x, const float* __restrict__ mod, float* __restrict__ out)
{
    int row = blockIdx.x;
    int b = row / SS_;
    const float* xr = x + (long long)row * DS_;
    const float* mrow = mod + (long long)b * 3 * DS_;
    float* orow = out + (long long)row * DS_;
    float ss = 0.f;
    for (int i = threadIdx.x; i < DS_; i += 256) { float v = xr[i]; ss = fmaf(v, v, ss); }
    __shared__ float sh[32];
    int lane = threadIdx.x & 31, wid = threadIdx.x >> 5;
#pragma unroll
    for (int o = 16; o > 0; o >>= 1) ss += __shfl_down_sync(0xffffffffu, ss, o);
    if (lane == 0) sh[wid] = ss;
    __syncthreads();
    if (threadIdx.x == 0) {
        float t = 0.f;
        for (int i = 0; i < 8; i++) t += sh[i];
        sh[0] = rsqrtf(t / (float)DS_ + EPS_);
    }
    __syncthreads();
    float r = sh[0];
    for (int i = threadIdx.x; i < DS_; i += 256)
        orow[i] = xr[i] * r * (1.0f + mrow[i]) + mrow[DS_ + i];
}

// ---------------- RoPE ----------------
__global__ void rope_kernel(float* __restrict__ q, float* __restrict__ k) {
    long long idx = (long long)blockIdx.x * blockDim.x + threadIdx.x;
    const long long NQ = (long long)B_ * NT_ * H_ * (HD_ / 2);
    const long long NK = (long long)B_ * NT_ * (HD_ / 2);
    const float LN_TH_OVER = 9.210340371976184f / 128.0f;
    if (idx < NQ) {
        int d = (int)(idx & 127); long long t = idx >> 7;
        int h = (int)(t % H_); t /= H_;
        int s = (int)(t % NT_); int b = (int)(t / NT_);
        float inv = expf(-(float)d * LN_TH_OVER);
        float ang = (float)s * inv;
        float c, sn; sincosf(ang, &sn, &c);
        float* pq = q + ((long long)(b * NT_ + s)) * (H_ * HD_) + h * HD_;
        float x1 = pq[d], x2 = pq[d + 128];
        pq[d]       = x1 * c - x2 * sn;
        pq[d + 128] = x2 * c + x1 * sn;
    } else if (idx < NQ + NK) {
        long long r = idx - NQ;
        int d = (int)(r & 127); long long t = r >> 7;
        int s = (int)(t % NT_); int b = (int)(t / NT_);
        float inv = expf(-(float)d * LN_TH_OVER);
        float ang = (float)s * inv;
        float c, sn; sincosf(ang, &sn, &c);
        float* pk = k + ((long long)(b * NT_ + s)) * HD_;
        float x1 = pk[d], x2 = pk[d + 128];
        pk[d]       = x1 * c - x2 * sn;
        pk[d + 128] = x2 * c + x1 * sn;
    }
}

// ---------------- softmax ----------------
__global__ __launch_bounds__(256) void softmax_kernel(float* __restrict__ sc) {
    long long row = blockIdx.x;
    float* p = sc + row * NT_;
    __shared__ float sh[32];
    int lane = threadIdx.x & 31, wid = threadIdx.x >> 5;

    float mx = -3.4e38f;
    for (int i = threadIdx.x; i < NT_; i += 256) mx = fmaxf(mx, p[i]);
#pragma unroll
    for (int o = 16; o > 0; o >>= 1) mx = fmaxf(mx, __shfl_down_sync(0xffffffffu, mx, o));
    if (lane == 0) sh[wid] = mx;
    __syncthreads();
    if (threadIdx.x == 0) {
        float t = -3.4e38f;
        for (int i = 0; i < 8; i++) t = fmaxf(t, sh[i]);
        sh[0] = t;
    }
    __syncthreads();
    mx = sh[0];
    __syncthreads();

    float sm = 0.f;
    for (int i = threadIdx.x; i < NT_; i += 256) {
        float e = expf(p[i] - mx);
        p[i] = e;
        sm += e;
    }
#pragma unroll
    for (int o = 16; o > 0; o >>= 1) sm += __shfl_down_sync(0xffffffffu, sm, o);
    if (lane == 0) sh[wid] = sm;
    __syncthreads();
    if (threadIdx.x == 0) {
        float t = 0.f;
        for (int i = 0; i < 8; i++) t += sh[i];
        sh[0] = 1.0f / t;
    }
    __syncthreads();
    float inv = sh[0];
    for (int i = threadIdx.x; i < NT_; i += 256) p[i] *= inv;
}

// ---------------- host side ----------------
static GemmP gp(const float* A, const float* Bm, float* C,
                int M, int N, int K, int lda, int ldb, int ldc) {
    GemmP p = {};
    p.A = A; p.Bm = Bm; p.C = C;
    p.M = M; p.N = N; p.K = K; p.lda = lda; p.ldb = ldb; p.ldc = ldc;
    p.zdiv = 1; p.alpha = 1.0f; p.rowsPerB = 1 << 30;
    return p;
}

static void launch_gemm(const GemmP& p, int batch) {
    dim3 grid((p.N + 127) / 128, (p.M + 127) / 128, batch);
    gemm_tc<<<grid, 256, SMEM_TOTAL>>>(p);
}

extern "C" void kernel_launch(void* const* d_in, const int* in_sizes, int n_in,
                              void* d_out, int out_size) {
    const float* prefix_x    = (const float*)d_in[0];
    const float* suffix_x    = (const float*)d_in[1];
    const float* cond        = (const float*)d_in[2];
    const float* p_ln_w      = (const float*)d_in[3];
    const float* p_q_w       = (const float*)d_in[4];
    const float* p_k_w       = (const float*)d_in[5];
    const float* p_v_w       = (const float*)d_in[6];
    const float* p_o_w       = (const float*)d_in[7];
    const float* p_post_ln_w = (const float*)d_in[8];
    const float* p_gate_w    = (const float*)d_in[9];
    const float* p_up_w      = (const float*)d_in[10];
    const float* p_down_w    = (const float*)d_in[11];
    const float* s_ada1_w    = (const float*)d_in[12];
    const float* s_ada1_b    = (const float*)d_in[13];
    const float* s_q_w       = (const float*)d_in[14];
    const float* s_k_w       = (const float*)d_in[15];
    const float* s_v_w       = (const float*)d_in[16];
    const float* s_o_w       = (const float*)d_in[17];
    const float* s_ada2_w    = (const float*)d_in[18];
    const float* s_ada2_b    = (const float*)d_in[19];
    const float* s_gate_w    = (const float*)d_in[20];
    const float* s_up_w      = (const float*)d_in[21];
    const float* s_down_w    = (const float*)d_in[22];
    float* out = (float*)d_out;

    cudaFuncSetAttribute(gemm_tc, cudaFuncAttributeMaxDynamicSharedMemorySize, SMEM_TOTAL);

    float *hp, *mod1, *mod2, *hs, *q, *k, *v, *sc, *ao, *resp, *act, *ress, *sact;
    cudaGetSymbolAddress((void**)&hp,   g_hp);
    cudaGetSymbolAddress((void**)&mod1, g_mod1);
    cudaGetSymbolAddress((void**)&mod2, g_mod2);
    cudaGetSymbolAddress((void**)&hs,   g_hs);
    cudaGetSymbolAddress((void**)&q,    g_q);
    cudaGetSymbolAddress((void**)&k,    g_k);
    cudaGetSymbolAddress((void**)&v,    g_v);
    cudaGetSymbolAddress((void**)&sc,   g_sc);
    cudaGetSymbolAddress((void**)&ao,   g_ao);
    cudaGetSymbolAddress((void**)&resp, g_resp);
    cudaGetSymbolAddress((void**)&act,  g_act);
    cudaGetSymbolAddress((void**)&ress, g_ress);
    cudaGetSymbolAddress((void**)&sact, g_sact);

    // 1. prefix gemma norm
    rmsnorm_gemma_kernel<<<B_ * SP_, 256>>>(prefix_x, p_ln_w, hp, DP_);

    // 2. adaLN modulation vectors
    {
        GemmP p = gp(cond, s_ada1_w, mod1, B_, 3 * DS_, DC_, DC_, DC_, 3 * DS_);
        p.epi = 1; p.bias = s_ada1_b;
        launch_gemm(p, 1);
        GemmP p2 = gp(cond, s_ada2_w, mod2, B_, 3 * DS_, DC_, DC_, DC_, 3 * DS_);
        p2.epi = 1; p2.bias = s_ada2_b;
        launch_gemm(p2, 1);
    }

    // 3. suffix adaLN #1
    ada_norm_kernel<<<B_ * SS_, 256>>>(suffix_x, mod1, hs);

    // 4. QKV projections
    {
        GemmP p = gp(hp, p_q_w, q, SP_, H_ * HD_, DP_, DP_, DP_, H_ * HD_);
        p.sA = (long long)SP_ * DP_; p.sC = (long long)NT_ * H_ * HD_;
        launch_gemm(p, B_);
    }
    {
        GemmP p = gp(hs, s_q_w, q + (long long)SP_ * H_ * HD_, SS_, H_ * HD_, DS_, DS_, DS_, H_ * HD_);
        p.sA = (long long)SS_ * DS_; p.sC = (long long)NT_ * H_ * HD_;
        launch_gemm(p, B_);
    }
    {
        GemmP p = gp(hp, p_k_w, k, SP_, HD_, DP_, DP_, DP_, HD_);
        p.sA = (long long)SP_ * DP_; p.sC = (long long)NT_ * HD_;
        launch_gemm(p, B_);
    }
    {
        GemmP p = gp(hs, s_k_w, k + (long long)SP_ * HD_, SS_, HD_, DS_, DS_, DS_, HD_);
        p.sA = (long long)SS_ * DS_; p.sC = (long long)NT_ * HD_;
        launch_gemm(p, B_);
    }
    {
        GemmP p = gp(hp, p_v_w, v, SP_, HD_, DP_, DP_, DP_, HD_);
        p.sA = (long long)SP_ * DP_; p.sC = (long long)NT_ * HD_;
        launch_gemm(p, B_);
    }
    {
        GemmP p = gp(hs, s_v_w, v + (long long)SP_ * HD_, SS_, HD_, DS_, DS_, DS_, HD_);
        p.sA = (long long)SS_ * DS_; p.sC = (long long)NT_ * HD_;
        launch_gemm(p, B_);
    }

    // 5. RoPE
    {
        long long total = (long long)B_ * NT_ * H_ * (HD_ / 2) + (long long)B_ * NT_ * (HD_ / 2);
        int blocks = (int)((total + 255) / 256);
        rope_kernel<<<blocks, 256>>>(q, k);
    }

    // 6. scores = QK^T/16 + mask
    {
        GemmP p = gp(q, k, sc, NT_, NT_, HD_, H_ * HD_, HD_, NT_);
        p.zdiv = H_;
        p.sA = (long long)NT_ * H_ * HD_; p.sA2 = HD_;
        p.sB = (long long)NT_ * HD_;      p.sB2 = 0;
        p.sC = (long long)H_ * NT_ * NT_; p.sC2 = (long long)NT_ * NT_;
        p.epi = 6; p.alpha = 0.0625f;
        launch_gemm(p, B_ * H_);
    }

    // 7. softmax
    softmax_kernel<<<B_ * H_ * NT_, 256>>>(sc);

    // 8. attn @ V
    {
        GemmP p = gp(sc, v, ao, NT_, HD_, NT_, NT_, HD_, H_ * HD_);
        p.zdiv = H_; p.transB = 1;
        p.sA = (long long)H_ * NT_ * NT_; p.sA2 = (long long)NT_ * NT_;
        p.sB = (long long)NT_ * HD_;      p.sB2 = 0;
        p.sC = (long long)NT_ * H_ * HD_; p.sC2 = HD_;
        launch_gemm(p, B_ * H_);
    }

    // 9. prefix O-proj + residual
    {
        GemmP p = gp(ao, p_o_w, resp, SP_, DP_, H_ * HD_, H_ * HD_, H_ * HD_, DP_);
        p.sA = (long long)NT_ * H_ * HD_; p.sC = (long long)SP_ * DP_;
        p.epi = 4; p.res = prefix_x; p.sRes = (long long)SP_ * DP_;
        launch_gemm(p, B_);
    }

    // 10. post-norm
    rmsnorm_gemma_kernel<<<B_ * SP_, 256>>>(resp, p_post_ln_w, hp, DP_);

    // 11-13. prefix MLP
    {
        GemmP p = gp(hp, p_gate_w, act, B_ * SP_, FP_, DP_, DP_, DP_, FP_);
        p.epi = 2;
        launch_gemm(p, 1);
    }
    {
        GemmP p = gp(hp, p_up_w, act, B_ * SP_, FP_, DP_, DP_, DP_, FP_);
        p.epi = 3;
        launch_gemm(p, 1);
    }
    {
        GemmP p = gp(act, p_down_w, out, B_ * SP_, DP_, FP_, FP_, FP_, DP_);
        p.epi = 4; p.res = resp; p.sRes = 0;
        launch_gemm(p, 1);
    }

    // 14. suffix O-proj with gate
    {
        GemmP p = gp(ao + (long long)SP_ * H_ * HD_, s_o_w, ress, SS_, DS_, H_ * HD_, H_ * HD_, H_ * HD_, DS_);
        p.sA = (long long)NT_ * H_ * HD_; p.sC = (long long)SS_ * DS_;
        p.epi = 5; p.res = suffix_x; p.sRes = (long long)SS_ * DS_;
        p.gate = mod1 + 2 * DS_; p.sGate = 3 * DS_; p.rowsPerB = 1 << 30; p.ldGate = 0;
        launch_gemm(p, B_);
    }

    // 15. suffix adaLN #2
    ada_norm_kernel<<<B_ * SS_, 256>>>(ress, mod2, hs);

    // 16-18. suffix MLP with gate2
    {
        GemmP p = gp(hs, s_gate_w, sact, B_ * SS_, FS_, DS_, DS_, DS_, FS_);
        p.epi = 2;
        launch_gemm(p, 1);
    }
    {
        GemmP p = gp(hs, s_up_w, sact, B_ * SS_, FS_, DS_, DS_, DS_, FS_);
        p.epi = 3;
        launch_gemm(p, 1);
    }
    {
        GemmP p = gp(sact, s_down_w, out + (long long)B_ * SP_ * DP_, B_ * SS_, DS_, FS_, FS_, FS_, DS_);
        p.epi = 5; p.res = ress; p.sRes = 0;
        p.gate = mod2 + 2 * DS_; p.sGate = 0; p.rowsPerB = SS_; p.ldGate = 3 * DS_;
        launch_gemm(p, 1);
    }
}

// round 15
// speedup vs baseline: 3.5287x; 1.3725x over previous
#include <cuda_runtime.h>
#include <cuda_bf16.h>
#include <math.h>
#include <stdint.h>

#define B_   8
#define SP_  800
#define SS_  48
#define NT_  848
#define DP_  2048
#define DS_  1024
#define DC_  1024
#define H_   8
#define HD_  256
#define FP_  16384
#define FS_  4096
#define EPS_ 1e-6f
#define MASKV_ (-2.3819763e+38f)

typedef __nv_bfloat16 bf16;

// ---------------- fp32 scratch ----------------
__device__ float g_mod1[B_*3*DS_];
__device__ float g_mod2[B_*3*DS_];
__device__ float g_q   [(size_t)B_*NT_*H_*HD_];
__device__ float g_k   [(size_t)B_*NT_*HD_];
__device__ float g_v   [(size_t)B_*NT_*HD_];
__device__ float g_sc  [(size_t)B_*H_*NT_*NT_];
__device__ float g_resp[(size_t)B_*SP_*DP_];
__device__ float g_act [(size_t)B_*SP_*FP_];
__device__ float g_ress[B_*SS_*DS_];

// ---------------- bf16 hi/lo pair buffers ----------------
__device__ bf16 g_hp_h[(size_t)B_*SP_*DP_],  g_hp_l[(size_t)B_*SP_*DP_];
__device__ bf16 g_hs_h[B_*SS_*DS_],          g_hs_l[B_*SS_*DS_];
__device__ bf16 g_cond_h[B_*DC_],            g_cond_l[B_*DC_];
__device__ bf16 g_qp_h[(size_t)B_*NT_*H_*HD_], g_qp_l[(size_t)B_*NT_*H_*HD_];
__device__ bf16 g_kp_h[(size_t)B_*NT_*HD_],  g_kp_l[(size_t)B_*NT_*HD_];
__device__ bf16 g_vT_h[(size_t)B_*NT_*HD_],  g_vT_l[(size_t)B_*NT_*HD_];
__device__ bf16 g_scp_h[(size_t)B_*H_*NT_*NT_], g_scp_l[(size_t)B_*H_*NT_*NT_];
__device__ bf16 g_ao_h[(size_t)B_*NT_*H_*HD_], g_ao_l[(size_t)B_*NT_*H_*HD_];
__device__ bf16 g_actp_h[(size_t)B_*SP_*FP_], g_actp_l[(size_t)B_*SP_*FP_];
__device__ bf16 g_sactp_h[B_*SS_*FS_],       g_sactp_l[B_*SS_*FS_];
// weights
__device__ bf16 g_qw_h[H_*HD_*DP_],  g_qw_l[H_*HD_*DP_];
__device__ bf16 g_kw_h[HD_*DP_],     g_kw_l[HD_*DP_];
__device__ bf16 g_vw_h[HD_*DP_],     g_vw_l[HD_*DP_];
__device__ bf16 g_ow_h[DP_*H_*HD_],  g_ow_l[DP_*H_*HD_];
__device__ bf16 g_gw_h[(size_t)FP_*DP_], g_gw_l[(size_t)FP_*DP_];
__device__ bf16 g_uw_h[(size_t)FP_*DP_], g_uw_l[(size_t)FP_*DP_];
__device__ bf16 g_dw_h[(size_t)DP_*FP_], g_dw_l[(size_t)DP_*FP_];
__device__ bf16 g_a1w_h[3*DS_*DC_],  g_a1w_l[3*DS_*DC_];
__device__ bf16 g_a2w_h[3*DS_*DC_],  g_a2w_l[3*DS_*DC_];
__device__ bf16 g_sqw_h[H_*HD_*DS_], g_sqw_l[H_*HD_*DS_];
__device__ bf16 g_skw_h[HD_*DS_],    g_skw_l[HD_*DS_];
__device__ bf16 g_svw_h[HD_*DS_],    g_svw_l[HD_*DS_];
__device__ bf16 g_sow_h[DS_*H_*HD_], g_sow_l[DS_*H_*HD_];
__device__ bf16 g_sgw_h[FS_*DS_],    g_sgw_l[FS_*DS_];
__device__ bf16 g_suw_h[FS_*DS_],    g_suw_l[FS_*DS_];
__device__ bf16 g_sdw_h[DS_*FS_],    g_sdw_l[DS_*FS_];

// ---------------- helpers ----------------
__device__ __forceinline__ uint32_t smem_u32(const void* p) {
    uint32_t a;
    asm("{ .reg .u64 t; cvta.to.shared.u64 t, %1; cvt.u32.u64 %0, t; }" : "=r"(a) : "l"(p));
    return a;
}
__device__ __forceinline__ void ldm_x4(uint32_t& r0, uint32_t& r1, uint32_t& r2, uint32_t& r3,
                                       uint32_t addr) {
    asm volatile("ldmatrix.sync.aligned.m8n8.x4.shared.b16 {%0,%1,%2,%3}, [%4];"
                 : "=r"(r0), "=r"(r1), "=r"(r2), "=r"(r3) : "r"(addr));
}
__device__ __forceinline__ void ldm_x2(uint32_t& r0, uint32_t& r1, uint32_t addr) {
    asm volatile("ldmatrix.sync.aligned.m8n8.x2.shared.b16 {%0,%1}, [%2];"
                 : "=r"(r0), "=r"(r1) : "r"(addr));
}
__device__ __forceinline__ void mma_bf16(float* c, uint32_t a0, uint32_t a1, uint32_t a2,
                                         uint32_t a3, uint32_t b0, uint32_t b1) {
    asm volatile("mma.sync.aligned.m16n8k16.row.col.f32.bf16.bf16.f32 "
                 "{%0,%1,%2,%3}, {%4,%5,%6,%7}, {%8,%9}, {%0,%1,%2,%3};"
                 : "+f"(c[0]), "+f"(c[1]), "+f"(c[2]), "+f"(c[3])
                 : "r"(a0), "r"(a1), "r"(a2), "r"(a3), "r"(b0), "r"(b1));
}
__device__ __forceinline__ float gelu_tanh(float x) {
    float x3 = x * x * x;
    return 0.5f * x * (1.0f + tanhf(0.7978845608028654f * (x + 0.044715f * x3)));
}
__device__ __forceinline__ void store_pair(bf16* h, bf16* l, long long i, float v) {
    bf16 hh = __float2bfloat16(v);
    h[i] = hh;
    l[i] = __float2bfloat16(v - __bfloat162float(hh));
}

// ---------------- GEMM params ----------------
struct GemmP {
    const bf16 *Ah, *Al, *Bh, *Bl;
    float* C;
    bf16 *Chi, *Clo; int pairOut;
    int M, N, K, lda, ldb, ldc;
    long long sA, sB, sC, sA2, sB2, sC2;
    int zdiv;
    int epi;       // 0 plain, 1 +bias, 2 gelu, 3 C*=acc, 4 +res, 5 res+acc*gate, 6 mask+scale
    float alpha;
    const float* bias;
    const float* res;  long long sRes;
    const float* gate; long long sGate; int rowsPerB; int ldGate;
};

// smem: per stage 4 arrays (Ahi, Alo, Bhi, Blo), each 128 rows x 64 B (32 bf16),
// swizzle: phys chunk = c ^ ((row>>1)&3)  -> conflict-free ldmatrix, 16B-aligned cp.async
#define STAGE_B   32768
#define SMEM_TOTAL (3 * STAGE_B)   // 98304

#define CP16(dst, src, sz) \
    asm volatile("cp.async.cg.shared.global [%0], [%1], 16, %2;" \
                 :: "r"(dst), "l"(src), "r"(sz) : "memory")
#define CP_COMMIT() asm volatile("cp.async.commit_group;" ::: "memory")
#define CP_WAIT2()  asm volatile("cp.async.wait_group 2;" ::: "memory")

// ---------------- HMMA GEMM: 128x128, 8 warps, bf16x3, cp.async 3-stage, 2 CTAs/SM ---
__global__ void __launch_bounds__(256, 2) gemm_tc(GemmP p) {
    extern __shared__ char smem[];
    const uint32_t sb = smem_u32(smem);
    const int tid  = threadIdx.x;
    const int wid  = tid >> 5, lane = tid & 31;
    const int gid  = lane >> 2, tig = lane & 3;
    const int wr   = wid >> 2, wc = wid & 3;

    const int z  = blockIdx.z;
    const int zb = z / p.zdiv, zr = z % p.zdiv;
    const long long aoff = (long long)zb * p.sA + (long long)zr * p.sA2;
    const long long boff = (long long)zb * p.sB + (long long)zr * p.sB2;
    const long long coff = (long long)zb * p.sC + (long long)zr * p.sC2;
    const bf16* Ah = p.Ah + aoff;
    const bf16* Al = p.Al + aoff;
    const bf16* Bh = p.Bh + boff;
    const bf16* Bl = p.Bl + boff;

    const int bm = blockIdx.y * 128;
    const int bn = blockIdx.x * 128;

    float acc[4][4][4];
#pragma unroll
    for (int i = 0; i < 4; i++)
#pragma unroll
        for (int j = 0; j < 4; j++)
#pragma unroll
            for (int r = 0; r < 4; r++) acc[i][j][r] = 0.f;

    const int nkt = (p.K + 31) >> 5;

    const int ar = wr * 64 + (lane & 15);
    const int ac = lane >> 4;            // A k-chunk half
    const int br = wc * 32 + (lane & 7);
    const int bc = (lane >> 3) & 1;      // B k-chunk half

    const int crow0 = tid >> 2;          // cp.async: base row
    const int cc    = tid & 3;           // cp.async: chunk

#define ISSUE_STAGE(kt_, st_) do {                                                      \
        const int kb_ = (kt_) << 5;                                                     \
        const uint32_t stb_ = sb + (uint32_t)(st_) * STAGE_B;                           \
        const int kpos_ = kb_ + cc * 8;                                                 \
        int kb2_ = (p.K - kpos_) * 2;                                                   \
        kb2_ = kb2_ < 0 ? 0 : (kb2_ > 16 ? 16 : kb2_);                                  \
        _Pragma("unroll")                                                               \
        for (int i = 0; i < 8; i++) {                                                   \
            const int arr_ = i >> 1;                                                    \
            const int row_ = (crow0 + 64 * i) & 127;                                    \
            const bf16* base_ = (arr_ == 0) ? Ah : (arr_ == 1) ? Al                     \
                              : (arr_ == 2) ? Bh : Bl;                                  \
            const int gr_   = ((arr_ < 2) ? bm : bn) + row_;                            \
            const int rmax_ = (arr_ < 2) ? p.M : p.N;                                   \
            const int ld_   = (arr_ < 2) ? p.lda : p.ldb;                               \
            const int ok_   = (gr_ < rmax_);                                            \
            const int sz_   = ok_ ? kb2_ : 0;                                           \
            const long long so_ = ok_ ? ((long long)gr_ * ld_ + kpos_) : 0;             \
            const uint32_t dst_ = stb_ + (uint32_t)(arr_ * 8192)                        \
                + (uint32_t)(row_ * 64 + (((cc ^ (row_ >> 1)) & 3) << 4));              \
            CP16(dst_, base_ + so_, sz_);                                               \
        }                                                                               \
        CP_COMMIT();                                                                    \
    } while (0)

    ISSUE_STAGE(0, 0);
    if (nkt > 1) ISSUE_STAGE(1, 1); else CP_COMMIT();
    if (nkt > 2) ISSUE_STAGE(2, 2); else CP_COMMIT();

    for (int kt = 0; kt < nkt; kt++) {
        CP_WAIT2();
        __syncthreads();
        const int s = kt % 3;
        const uint32_t stb = sb + (uint32_t)s * STAGE_B;
        const uint32_t sAh_ = stb, sAl_ = stb + 8192, sBh_ = stb + 16384, sBl_ = stb + 24576;
#pragma unroll
        for (int k16 = 0; k16 < 2; k16++) {
            uint32_t bhf[4][2], blf[4][2];
#pragma unroll
            for (int nn = 0; nn < 4; nn++) {
                int rowb = br + nn * 8;
                uint32_t off = (uint32_t)(rowb * 64
                    + ((((k16 * 2 + bc) ^ (rowb >> 1)) & 3) << 4));
                ldm_x2(bhf[nn][0], bhf[nn][1], sBh_ + off);
                ldm_x2(blf[nn][0], blf[nn][1], sBl_ + off);
            }
#pragma unroll
            for (int mm = 0; mm < 4; mm++) {
                int rowa = ar + mm * 16;
                uint32_t off = (uint32_t)(rowa * 64
                    + ((((k16 * 2 + ac) ^ (rowa >> 1)) & 3) << 4));
                uint32_t ah0, ah1, ah2, ah3, al0, al1, al2, al3;
                ldm_x4(ah0, ah1, ah2, ah3, sAh_ + off);
                ldm_x4(al0, al1, al2, al3, sAl_ + off);
#pragma unroll
                for (int nn = 0; nn < 4; nn++) {
                    mma_bf16(acc[mm][nn], ah0, ah1, ah2, ah3, bhf[nn][0], bhf[nn][1]);
                    mma_bf16(acc[mm][nn], al0, al1, al2, al3, bhf[nn][0], bhf[nn][1]);
                    mma_bf16(acc[mm][nn], ah0, ah1, ah2, ah3, blf[nn][0], blf[nn][1]);
                }
            }
        }
        __syncthreads();
        if (kt + 3 < nkt) ISSUE_STAGE(kt + 3, s); else CP_COMMIT();
    }

    // ---------------- epilogue ----------------
    float* Cz = p.C + coff;
#pragma unroll
    for (int mm = 0; mm < 4; mm++) {
#pragma unroll
        for (int rr = 0; rr < 2; rr++) {
            int m = bm + wr * 64 + mm * 16 + gid + rr * 8;
            if (m >= p.M) continue;
#pragma unroll
            for (int nn = 0; nn < 4; nn++) {
#pragma unroll
                for (int c2 = 0; c2 < 2; c2++) {
                    int n = bn + wc * 32 + nn * 8 + tig * 2 + c2;
                    if (n >= p.N) continue;
                    float v = acc[mm][nn][rr * 2 + c2] * p.alpha;
                    long long cidx = (long long)m * p.ldc + n;
                    switch (p.epi) {
                        case 1: v += p.bias[n]; break;
                        case 2: v = gelu_tanh(v); break;
                        case 3: v = Cz[cidx] * v; break;
                        case 4: v += p.res[(long long)zb * p.sRes + cidx]; break;
                        case 5: v = p.res[(long long)zb * p.sRes + cidx]
                                    + v * p.gate[(long long)zb * p.sGate
                                                 + (long long)(m / p.rowsPerB) * p.ldGate + n];
                                break;
                        case 6: if (m < SP_ && n >= SP_) v += MASKV_; break;
                        default: break;
                    }
                    if (p.pairOut) store_pair(p.Chi + coff, p.Clo + coff, cidx, v);
                    else Cz[cidx] = v;
                }
            }
        }
    }
}

// ---------------- conversion kernels ----------------
__global__ void cvt_pair_kernel(const float* __restrict__ x, bf16* __restrict__ h,
                                bf16* __restrict__ l, long long n) {
    long long i = (long long)blockIdx.x * blockDim.x + threadIdx.x;
    if (i < n) store_pair(h, l, i, x[i]);
}

__global__ void cvt_pairT_kernel(const float* __restrict__ v, bf16* __restrict__ h,
                                 bf16* __restrict__ l) {
    long long i = (long long)blockIdx.x * blockDim.x + threadIdx.x;
    const long long n = (long long)B_ * NT_ * HD_;
    if (i >= n) return;
    int d = (int)(i % HD_); long long t = i / HD_;
    int s = (int)(t % NT_); int b = (int)(t / NT_);
    long long o = ((long long)b * HD_ + d) * NT_ + s;
    store_pair(h, l, o, v[i]);
}

// ---------------- RMS norms (pair output) ----------------
__global__ __launch_bounds__(256) void rmsnorm_pair_kernel(
    const float* __restrict__ x, const float* __restrict__ w,
    bf16* __restrict__ oh, bf16* __restrict__ ol, int D)
{
    long long row = blockIdx.x;
    const float* xr = x + row * D;
    float ss = 0.f;
    for (int i = threadIdx.x; i < D; i += 256) { float v = xr[i]; ss = fmaf(v, v, ss); }
    __shared__ float sh[32];
    int lane = threadIdx.x & 31, wid = threadIdx.x >> 5;
#pragma unroll
    for (int o = 16; o > 0; o >>= 1) ss += __shfl_down_sync(0xffffffffu, ss, o);
    if (lane == 0) sh[wid] = ss;
    __syncthreads();
    if (threadIdx.x == 0) {
        float t = 0.f;
        for (int i = 0; i < 8; i++) t += sh[i];
        sh[0] = rsqrtf(t / (float)D + EPS_);
    }
    __syncthreads();
    float r = sh[0];
    for (int i = threadIdx.x; i < D; i += 256)
        store_pair(oh, ol, row * D + i, xr[i] * r * (1.0f + w[i]));
}

__global__ __launch_bounds__(256) void ada_norm_pair_kernel(
    const float* __restrict__ x, const float* __restrict__ mod,
    bf16* __restrict__ oh, bf16* __restrict__ ol)
{
    int row = blockIdx.x;
    int b = row / SS_;
    const float* xr = x + (long long)row * DS_;
    const float* mrow = mod + (long long)b * 3 * DS_;
    float ss = 0.f;
    for (int i = threadIdx.x; i < DS_; i += 256) { float v = xr[i]; ss = fmaf(v, v, ss); }
    __shared__ float sh[32];
    int lane = threadIdx.x & 31, wid = threadIdx.x >> 5;
#pragma unroll
    for (int o = 16; o > 0; o >>= 1) ss += __shfl_down_sync(0xffffffffu, ss, o);
    if (lane == 0) sh[wid] = ss;
    __syncthreads();
    if (threadIdx.x == 0) {
        float t = 0.f;
        for (int i = 0; i < 8; i++) t += sh[i];
        sh[0] = rsqrtf(t / (float)DS_ + EPS_);
    }
    __syncthreads();
    float r = sh[0];
    for (int i = threadIdx.x; i < DS_; i += 256)
        store_pair(oh, ol, (long long)row * DS_ + i,
                   xr[i] * r * (1.0f + mrow[i]) + mrow[DS_ + i]);
}

// ---------------- RoPE (fp32 in, pair out) ----------------
__global__ void rope_pair_kernel(const float* __restrict__ q, const float* __restrict__ k,
                                 bf16* __restrict__ qh, bf16* __restrict__ ql,
                                 bf16* __restrict__ kh, bf16* __restrict__ kl) {
    long long idx = (long long)blockIdx.x * blockDim.x + threadIdx.x;
    const long long NQ = (long long)B_ * NT_ * H_ * (HD_ / 2);
    const long long NK = (long long)B_ * NT_ * (HD_ / 2);
    const float LN_TH_OVER = 9.210340371976184f / 128.0f;
    if (idx < NQ) {
        int d = (int)(idx & 127); long long t = idx >> 7;
        int h = (int)(t % H_); t /= H_;
        int s = (int)(t % NT_); int b = (int)(t / NT_);
        float inv = expf(-(float)d * LN_TH_OVER);
        float ang = (float)s * inv;
        float c, sn; sincosf(ang, &sn, &c);
        long long base = ((long long)(b * NT_ + s)) * (H_ * HD_) + h * HD_;
        float x1 = q[base + d], x2 = q[base + d + 128];
        store_pair(qh, ql, base + d,       x1 * c - x2 * sn);
        store_pair(qh, ql, base + d + 128, x2 * c + x1 * sn);
    } else if (idx < NQ + NK) {
        long long r = idx - NQ;
        int d = (int)(r & 127); long long t = r >> 7;
        int s = (int)(t % NT_); int b = (int)(t / NT_);
        float inv = expf(-(float)d * LN_TH_OVER);
        float ang = (float)s * inv;
        float c, sn; sincosf(ang, &sn, &c);
        long long base = ((long long)(b * NT_ + s)) * HD_;
        float x1 = k[base + d], x2 = k[base + d + 128];
        store_pair(kh, kl, base + d,       x1 * c - x2 * sn);
        store_pair(kh, kl, base + d + 128, x2 * c + x1 * sn);
    }
}

// ---------------- softmax (fp32 in, pair out) ----------------
__global__ __launch_bounds__(256) void softmax_pair_kernel(
    float* __restrict__ sc, bf16* __restrict__ oh, bf16* __restrict__ ol)
{
    long long row = blockIdx.x;
    float* p = sc + row * NT_;
    __shared__ float sh[32];
    int lane = threadIdx.x & 31, wid = threadIdx.x >> 5;

    float mx = -3.4e38f;
    for (int i = threadIdx.x; i < NT_; i += 256) mx = fmaxf(mx, p[i]);
#pragma unroll
    for (int o = 16; o > 0; o >>= 1) mx = fmaxf(mx, __shfl_down_sync(0xffffffffu, mx, o));
    if (lane == 0) sh[wid] = mx;
    __syncthreads();
    if (threadIdx.x == 0) {
        float t = -3.4e38f;
        for (int i = 0; i < 8; i++) t = fmaxf(t, sh[i]);
        sh[0] = t;
    }
    __syncthreads();
    mx = sh[0];
    __syncthreads();

    float sm = 0.f;
    for (int i = threadIdx.x; i < NT_; i += 256) {
        float e = expf(p[i] - mx);
        p[i] = e;
        sm += e;
    }
#pragma unroll
    for (int o = 16; o > 0; o >>= 1) sm += __shfl_down_sync(0xffffffffu, sm, o);
    if (lane == 0) sh[wid] = sm;
    __syncthreads();
    if (threadIdx.x == 0) {
        float t = 0.f;
        for (int i = 0; i < 8; i++) t += sh[i];
        sh[0] = 1.0f / t;
    }
    __syncthreads();
    float inv = sh[0];
    for (int i = threadIdx.x; i < NT_; i += 256)
        store_pair(oh, ol, row * NT_ + i, p[i] * inv);
}

// ---------------- host side ----------------
static GemmP gp(const bf16* Ah, const bf16* Al, const bf16* Bh, const bf16* Bl,
                float* C, int M, int N, int K, int lda, int ldb, int ldc) {
    GemmP p = {};
    p.Ah = Ah; p.Al = Al; p.Bh = Bh; p.Bl = Bl; p.C = C;
    p.M = M; p.N = N; p.K = K; p.lda = lda; p.ldb = ldb; p.ldc = ldc;
    p.zdiv = 1; p.alpha = 1.0f; p.rowsPerB = 1 << 30;
    return p;
}

static void launch_gemm(const GemmP& p, int batch) {
    dim3 grid((p.N + 127) / 128, (p.M + 127) / 128, batch);
    gemm_tc<<<grid, 256, SMEM_TOTAL>>>(p);
}

static void cvt(const float* src, bf16* h, bf16* l, long long n) {
    int blocks = (int)((n + 255) / 256);
    cvt_pair_kernel<<<blocks, 256>>>(src, h, l, n);
}

#define SYM(v, s) cudaGetSymbolAddress((void**)&v, s)

extern "C" void kernel_launch(void* const* d_in, const int* in_sizes, int n_in,
                              void* d_out, int out_size) {
    const float* prefix_x    = (const float*)d_in[0];
    const float* suffix_x    = (const float*)d_in[1];
    const float* cond        = (const float*)d_in[2];
    const float* p_ln_w      = (const float*)d_in[3];
    const float* p_q_w       = (const float*)d_in[4];
    const float* p_k_w       = (const float*)d_in[5];
    const float* p_v_w       = (const float*)d_in[6];
    const float* p_o_w       = (const float*)d_in[7];
    const float* p_post_ln_w = (const float*)d_in[8];
    const float* p_gate_w    = (const float*)d_in[9];
    const float* p_up_w      = (const float*)d_in[10];
    const float* p_down_w    = (const float*)d_in[11];
    const float* s_ada1_w    = (const float*)d_in[12];
    const float* s_ada1_b    = (const float*)d_in[13];
    const float* s_q_w       = (const float*)d_in[14];
    const float* s_k_w       = (const float*)d_in[15];
    const float* s_v_w       = (const float*)d_in[16];
    const float* s_o_w       = (const float*)d_in[17];
    const float* s_ada2_w    = (const float*)d_in[18];
    const float* s_ada2_b    = (const float*)d_in[19];
    const float* s_gate_w    = (const float*)d_in[20];
    const float* s_up_w      = (const float*)d_in[21];
    const float* s_down_w    = (const float*)d_in[22];
    float* out = (float*)d_out;

    cudaFuncSetAttribute(gemm_tc, cudaFuncAttributeMaxDynamicSharedMemorySize, SMEM_TOTAL);

    float *mod1, *mod2, *q, *k, *v, *sc, *resp, *act, *ress;
    SYM(mod1, g_mod1); SYM(mod2, g_mod2); SYM(q, g_q); SYM(k, g_k); SYM(v, g_v);
    SYM(sc, g_sc); SYM(resp, g_resp); SYM(act, g_act); SYM(ress, g_ress);

    bf16 *hp_h,*hp_l,*hs_h,*hs_l,*cond_h,*cond_l,*qp_h,*qp_l,*kp_h,*kp_l,*vT_h,*vT_l;
    bf16 *scp_h,*scp_l,*ao_h,*ao_l,*actp_h,*actp_l,*sactp_h,*sactp_l;
    SYM(hp_h, g_hp_h); SYM(hp_l, g_hp_l); SYM(hs_h, g_hs_h); SYM(hs_l, g_hs_l);
    SYM(cond_h, g_cond_h); SYM(cond_l, g_cond_l);
    SYM(qp_h, g_qp_h); SYM(qp_l, g_qp_l); SYM(kp_h, g_kp_h); SYM(kp_l, g_kp_l);
    SYM(vT_h, g_vT_h); SYM(vT_l, g_vT_l);
    SYM(scp_h, g_scp_h); SYM(scp_l, g_scp_l); SYM(ao_h, g_ao_h); SYM(ao_l, g_ao_l);
    SYM(actp_h, g_actp_h); SYM(actp_l, g_actp_l);
    SYM(sactp_h, g_sactp_h); SYM(sactp_l, g_sactp_l);

    bf16 *qw_h,*qw_l,*kw_h,*kw_l,*vw_h,*vw_l,*ow_h,*ow_l,*gw_h,*gw_l,*uw_h,*uw_l,*dw_h,*dw_l;
    bf16 *a1w_h,*a1w_l,*a2w_h,*a2w_l,*sqw_h,*sqw_l,*skw_h,*skw_l,*svw_h,*svw_l;
    bf16 *sow_h,*sow_l,*sgw_h,*sgw_l,*suw_h,*suw_l,*sdw_h,*sdw_l;
    SYM(qw_h, g_qw_h); SYM(qw_l, g_qw_l); SYM(kw_h, g_kw_h); SYM(kw_l, g_kw_l);
    SYM(vw_h, g_vw_h); SYM(vw_l, g_vw_l); SYM(ow_h, g_ow_h); SYM(ow_l, g_ow_l);
    SYM(gw_h, g_gw_h); SYM(gw_l, g_gw_l); SYM(uw_h, g_uw_h); SYM(uw_l, g_uw_l);
    SYM(dw_h, g_dw_h); SYM(dw_l, g_dw_l);
    SYM(a1w_h, g_a1w_h); SYM(a1w_l, g_a1w_l); SYM(a2w_h, g_a2w_h); SYM(a2w_l, g_a2w_l);
    SYM(sqw_h, g_sqw_h); SYM(sqw_l, g_sqw_l); SYM(skw_h, g_skw_h); SYM(skw_l, g_skw_l);
    SYM(svw_h, g_svw_h); SYM(svw_l, g_svw_l); SYM(sow_h, g_sow_h); SYM(sow_l, g_sow_l);
    SYM(sgw_h, g_sgw_h); SYM(sgw_l, g_sgw_l); SYM(suw_h, g_suw_h); SYM(suw_l, g_suw_l);
    SYM(sdw_h, g_sdw_h); SYM(sdw_l, g_sdw_l);

    // 0. preconvert weights + cond
    cvt(p_q_w,    qw_h,  qw_l,  (long long)H_*HD_*DP_);
    cvt(p_k_w,    kw_h,  kw_l,  (long long)HD_*DP_);
    cvt(p_v_w,    vw_h,  vw_l,  (long long)HD_*DP_);
    cvt(p_o_w,    ow_h,  ow_l,  (long long)DP_*H_*HD_);
    cvt(p_gate_w, gw_h,  gw_l,  (long long)FP_*DP_);
    cvt(p_up_w,   uw_h,  uw_l,  (long long)FP_*DP_);
    cvt(p_down_w, dw_h,  dw_l,  (long long)DP_*FP_);
    cvt(s_ada1_w, a1w_h, a1w_l, (long long)3*DS_*DC_);
    cvt(s_ada2_w, a2w_h, a2w_l, (long long)3*DS_*DC_);
    cvt(s_q_w,    sqw_h, sqw_l, (long long)H_*HD_*DS_);
    cvt(s_k_w,    skw_h, skw_l, (long long)HD_*DS_);
    cvt(s_v_w,    svw_h, svw_l, (long long)HD_*DS_);
    cvt(s_o_w,    sow_h, sow_l, (long long)DS_*H_*HD_);
    cvt(s_gate_w, sgw_h, sgw_l, (long long)FS_*DS_);
    cvt(s_up_w,   suw_h, suw_l, (long long)FS_*DS_);
    cvt(s_down_w, sdw_h, sdw_l, (long long)DS_*FS_);
    cvt(cond,     cond_h, cond_l, (long long)B_*DC_);

    // 1. prefix gemma norm -> pairs
    rmsnorm_pair_kernel<<<B_ * SP_, 256>>>(prefix_x, p_ln_w, hp_h, hp_l, DP_);

    // 2. adaLN modulation vectors (fp32)
    {
        GemmP p = gp(cond_h, cond_l, a1w_h, a1w_l, mod1, B_, 3 * DS_, DC_, DC_, DC_, 3 * DS_);
        p.epi = 1; p.bias = s_ada1_b;
        launch_gemm(p, 1);
        GemmP p2 = gp(cond_h, cond_l, a2w_h, a2w_l, mod2, B_, 3 * DS_, DC_, DC_, DC_, 3 * DS_);
        p2.epi = 1; p2.bias = s_ada2_b;
        launch_gemm(p2, 1);
    }

    // 3. suffix adaLN #1 -> pairs
    ada_norm_pair_kernel<<<B_ * SS_, 256>>>(suffix_x, mod1, hs_h, hs_l);

    // 4. QKV projections (fp32 out; rope converts q,k; cvtT converts v)
    {
        GemmP p = gp(hp_h, hp_l, qw_h, qw_l, q, SP_, H_ * HD_, DP_, DP_, DP_, H_ * HD_);
        p.sA = (long long)SP_ * DP_; p.sC = (long long)NT_ * H_ * HD_;
        launch_gemm(p, B_);
    }
    {
        GemmP p = gp(hs_h, hs_l, sqw_h, sqw_l, q + (long long)SP_ * H_ * HD_,
                     SS_, H_ * HD_, DS_, DS_, DS_, H_ * HD_);
        p.sA = (long long)SS_ * DS_; p.sC = (long long)NT_ * H_ * HD_;
        launch_gemm(p, B_);
    }
    {
        GemmP p = gp(hp_h, hp_l, kw_h, kw_l, k, SP_, HD_, DP_, DP_, DP_, HD_);
        p.sA = (long long)SP_ * DP_; p.sC = (long long)NT_ * HD_;
        launch_gemm(p, B_);
    }
    {
        GemmP p = gp(hs_h, hs_l, skw_h, skw_l, k + (long long)SP_ * HD_,
                     SS_, HD_, DS_, DS_, DS_, HD_);
        p.sA = (long long)SS_ * DS_; p.sC = (long long)NT_ * HD_;
        launch_gemm(p, B_);
    }
    {
        GemmP p = gp(hp_h, hp_l, vw_h, vw_l, v, SP_, HD_, DP_, DP_, DP_, HD_);
        p.sA = (long long)SP_ * DP_; p.sC = (long long)NT_ * HD_;
        launch_gemm(p, B_);
    }
    {
        GemmP p = gp(hs_h, hs_l, svw_h, svw_l, v + (long long)SP_ * HD_,
                     SS_, HD_, DS_, DS_, DS_, HD_);
        p.sA = (long long)SS_ * DS_; p.sC = (long long)NT_ * HD_;
        launch_gemm(p, B_);
    }

    // 5. RoPE -> q,k pairs; V transpose -> pairs
    {
        long long total = (long long)B_ * NT_ * H_ * (HD_ / 2) + (long long)B_ * NT_ * (HD_ / 2);
        int blocks = (int)((total + 255) / 256);
        rope_pair_kernel<<<blocks, 256>>>(q, k, qp_h, qp_l, kp_h, kp_l);
        long long nv = (long long)B_ * NT_ * HD_;
        cvt_pairT_kernel<<<(int)((nv + 255) / 256), 256>>>(v, vT_h, vT_l);
    }

    // 6. scores = QK^T/16 + mask (fp32)
    {
        GemmP p = gp(qp_h, qp_l, kp_h, kp_l, sc, NT_, NT_, HD_, H_ * HD_, HD_, NT_);
        p.zdiv = H_;
        p.sA = (long long)NT_ * H_ * HD_; p.sA2 = HD_;
        p.sB = (long long)NT_ * HD_;      p.sB2 = 0;
        p.sC = (long long)H_ * NT_ * NT_; p.sC2 = (long long)NT_ * NT_;
        p.epi = 6; p.alpha = 0.0625f;
        launch_gemm(p, B_ * H_);
    }

    // 7. softmax -> prob pairs
    softmax_pair_kernel<<<B_ * H_ * NT_, 256>>>(sc, scp_h, scp_l);

    // 8. attn @ V (B = transposed V pairs) -> ao pairs
    {
        GemmP p = gp(scp_h, scp_l, vT_h, vT_l, resp /*unused*/, NT_, HD_, NT_, NT_, NT_, H_ * HD_);
        p.zdiv = H_;
        p.sA = (long long)H_ * NT_ * NT_; p.sA2 = (long long)NT_ * NT_;
        p.sB = (long long)HD_ * NT_;      p.sB2 = 0;
        p.sC = (long long)NT_ * H_ * HD_; p.sC2 = HD_;
        p.pairOut = 1; p.Chi = ao_h; p.Clo = ao_l;
        launch_gemm(p, B_ * H_);
    }

    // 9. prefix O-proj + residual (fp32)
    {
        GemmP p = gp(ao_h, ao_l, ow_h, ow_l, resp, SP_, DP_, H_ * HD_, H_ * HD_, H_ * HD_, DP_);
        p.sA = (long long)NT_ * H_ * HD_; p.sC = (long long)SP_ * DP_;
        p.epi = 4; p.res = prefix_x; p.sRes = (long long)SP_ * DP_;
        launch_gemm(p, B_);
    }

    // 10. post-norm -> hp pairs (reuse)
    rmsnorm_pair_kernel<<<B_ * SP_, 256>>>(resp, p_post_ln_w, hp_h, hp_l, DP_);

    // 11-13. prefix MLP
    {
        GemmP p = gp(hp_h, hp_l, gw_h, gw_l, act, B_ * SP_, FP_, DP_, DP_, DP_, FP_);
        p.epi = 2;
        launch_gemm(p, 1);
    }
    {
        GemmP p = gp(hp_h, hp_l, uw_h, uw_l, act, B_ * SP_, FP_, DP_, DP_, DP_, FP_);
        p.epi = 3; p.pairOut = 1; p.Chi = actp_h; p.Clo = actp_l;
        launch_gemm(p, 1);
    }
    {
        GemmP p = gp(actp_h, actp_l, dw_h, dw_l, out, B_ * SP_, DP_, FP_, FP_, FP_, DP_);
        p.epi = 4; p.res = resp; p.sRes = 0;
        launch_gemm(p, 1);
    }

    // 14. suffix O-proj with gate (fp32)
    {
        GemmP p = gp(ao_h + (long long)SP_ * H_ * HD_, ao_l + (long long)SP_ * H_ * HD_,
                     sow_h, sow_l, ress, SS_, DS_, H_ * HD_, H_ * HD_, H_ * HD_, DS_);
        p.sA = (long long)NT_ * H_ * HD_; p.sC = (long long)SS_ * DS_;
        p.epi = 5; p.res = suffix_x; p.sRes = (long long)SS_ * DS_;
        p.gate = mod1 + 2 * DS_; p.sGate = 3 * DS_; p.rowsPerB = 1 << 30; p.ldGate = 0;
        launch_gemm(p, B_);
    }

    // 15. suffix adaLN #2 -> hs pairs (reuse)
    ada_norm_pair_kernel<<<B_ * SS_, 256>>>(ress, mod2, hs_h, hs_l);

    // 16-18. suffix MLP with gate2
    {
        GemmP p = gp(hs_h, hs_l, sgw_h, sgw_l, act, B_ * SS_, FS_, DS_, DS_, DS_, FS_);
        p.epi = 2;
        launch_gemm(p, 1);
    }
    {
        GemmP p = gp(hs_h, hs_l, suw_h, suw_l, act, B_ * SS_, FS_, DS_, DS_, DS_, FS_);
        p.epi = 3; p.pairOut = 1; p.Chi = sactp_h; p.Clo = sactp_l;
        launch_gemm(p, 1);
    }
    {
        GemmP p = gp(sactp_h, sactp_l, sdw_h, sdw_l, out + (long long)B_ * SP_ * DP_,
                     B_ * SS_, DS_, FS_, FS_, FS_, DS_);
        p.epi = 5; p.res = ress; p.sRes = 0;
        p.gate = mod2 + 2 * DS_; p.sGate = 0; p.rowsPerB = SS_; p.ldGate = 3 * DS_;
        launch_gemm(p, 1);
    }
}